// round 1
// baseline (speedup 1.0000x reference)
#include <cuda_runtime.h>

#define NN 100000
#define EE 1600000
#define HH 128

// ---- scratch (device globals; allocation inside kernel_launch is forbidden) ----
static __device__ float g_buf[(size_t)NN * HH];   // scaled GEMM output: (h@W)*dinv[row]
static __device__ float h_buf[(size_t)NN * HH];   // layer activations (relu'd)
static __device__ float d_dinv[NN];
static __device__ int   d_deg[NN];
static __device__ int   d_rowstart[NN + 1];
static __device__ int   d_cursor[NN];
static __device__ int   d_srcs[EE];               // edge sources sorted by dst (CSR)

// ---------------------------------------------------------------- CSR build
__global__ void k_zero_deg() {
    int i = blockIdx.x * blockDim.x + threadIdx.x;
    if (i < NN) d_deg[i] = 0;
}

__global__ void k_count(const int* __restrict__ dst) {
    int e = blockIdx.x * blockDim.x + threadIdx.x;
    if (e < EE) atomicAdd(&d_deg[dst[e]], 1);
}

// Single-block sequential-chunk scan: exclusive prefix over d_deg -> row_start,
// cursor; also dinv = rsqrt(deg+1).
__global__ void k_scan() {
    __shared__ int s[1024];
    __shared__ int s_carry;
    int tid = threadIdx.x;
    int running = 0;
    const int chunks = (NN + 1023) >> 10;
    for (int c = 0; c < chunks; ++c) {
        int gi = (c << 10) + tid;
        int v = (gi < NN) ? d_deg[gi] : 0;
        int acc = v;
        s[tid] = acc;
        __syncthreads();
        for (int off = 1; off < 1024; off <<= 1) {
            int t = (tid >= off) ? s[tid - off] : 0;
            __syncthreads();
            acc += t;
            s[tid] = acc;
            __syncthreads();
        }
        if (gi < NN) {
            int excl = running + acc - v;
            d_rowstart[gi] = excl;
            d_cursor[gi]   = excl;
            d_dinv[gi]     = rsqrtf((float)(v + 1));
        }
        if (tid == 1023) s_carry = running + acc;
        __syncthreads();
        running = s_carry;
        __syncthreads();
    }
    if (tid == 0) d_rowstart[NN] = running;
}

__global__ void k_scatter(const int* __restrict__ src, const int* __restrict__ dst) {
    int e = blockIdx.x * blockDim.x + threadIdx.x;
    if (e < EE) {
        int d = dst[e];
        int p = atomicAdd(&d_cursor[d], 1);
        d_srcs[p] = src[e];
    }
}

// ---------------------------------------------------------------- GEMM
// g_buf[row] = (A[row] @ W) * dinv[row].  A = xin if non-null else h_buf.
// Block: 256 threads -> 128 rows x 128 cols tile; thread: 8x8 micro-tile.
__global__ void __launch_bounds__(256, 2)
k_gemm(const float* __restrict__ xin, const float* __restrict__ W) {
    const float* A = xin ? xin : (const float*)h_buf;
    __shared__ float As[16][128];   // As[k][row]  (A transposed in smem)
    __shared__ float Bs[16][128];   // Bs[k][col]
    int tid  = threadIdx.x;
    int row0 = blockIdx.x * 128;
    int tr = tid >> 4;   // 0..15 -> rows tr*8..tr*8+7
    int tc = tid & 15;   // 0..15 -> cols tc*8..tc*8+7

    float acc[8][8];
#pragma unroll
    for (int i = 0; i < 8; i++)
#pragma unroll
        for (int j = 0; j < 8; j++) acc[i][j] = 0.f;

    for (int kc = 0; kc < HH; kc += 16) {
        // stage A chunk (128 rows x 16 k), transposed into As[k][row]
#pragma unroll
        for (int q = 0; q < 2; q++) {
            int t2 = tid * 2 + q;          // 0..511
            int r  = t2 >> 2;              // 0..127
            int k4 = (t2 & 3) * 4;         // 0,4,8,12
            int grow = row0 + r;
            float4 v = make_float4(0.f, 0.f, 0.f, 0.f);
            if (grow < NN)
                v = *reinterpret_cast<const float4*>(A + (size_t)grow * HH + kc + k4);
            As[k4 + 0][r] = v.x; As[k4 + 1][r] = v.y;
            As[k4 + 2][r] = v.z; As[k4 + 3][r] = v.w;
        }
        // stage B chunk (16 k x 128 cols)
#pragma unroll
        for (int q = 0; q < 2; q++) {
            int t2 = tid * 2 + q;
            int k  = t2 >> 5;              // 0..15
            int j4 = (t2 & 31) * 4;        // 0..124
            *reinterpret_cast<float4*>(&Bs[k][j4]) =
                *reinterpret_cast<const float4*>(W + (size_t)(kc + k) * HH + j4);
        }
        __syncthreads();
#pragma unroll
        for (int k = 0; k < 16; k++) {
            float a[8], b[8];
            *reinterpret_cast<float4*>(&a[0]) = *reinterpret_cast<const float4*>(&As[k][tr * 8]);
            *reinterpret_cast<float4*>(&a[4]) = *reinterpret_cast<const float4*>(&As[k][tr * 8 + 4]);
            *reinterpret_cast<float4*>(&b[0]) = *reinterpret_cast<const float4*>(&Bs[k][tc * 8]);
            *reinterpret_cast<float4*>(&b[4]) = *reinterpret_cast<const float4*>(&Bs[k][tc * 8 + 4]);
#pragma unroll
            for (int i = 0; i < 8; i++)
#pragma unroll
                for (int j = 0; j < 8; j++)
                    acc[i][j] = fmaf(a[i], b[j], acc[i][j]);
        }
        __syncthreads();
    }
    // epilogue: scale by dinv[row], write g_buf
#pragma unroll
    for (int i = 0; i < 8; i++) {
        int grow = row0 + tr * 8 + i;
        if (grow < NN) {
            float dv = d_dinv[grow];
            float4 o0, o1;
            o0.x = acc[i][0] * dv; o0.y = acc[i][1] * dv;
            o0.z = acc[i][2] * dv; o0.w = acc[i][3] * dv;
            o1.x = acc[i][4] * dv; o1.y = acc[i][5] * dv;
            o1.z = acc[i][6] * dv; o1.w = acc[i][7] * dv;
            *reinterpret_cast<float4*>(&g_buf[(size_t)grow * HH + tc * 8])     = o0;
            *reinterpret_cast<float4*>(&g_buf[(size_t)grow * HH + tc * 8 + 4]) = o1;
        }
    }
}

// ---------------------------------------------------------------- aggregation
// out[i] = dinv[i] * (g[i] + sum_{e in in-edges(i)} g[src_e]) + bias + x[i]
// warp per node; lane handles 4 contiguous cols (float4).
__global__ void k_agg(const float* __restrict__ x, const float* __restrict__ bias,
                      float* __restrict__ outp, int relu, int to_out) {
    int gtid = blockIdx.x * blockDim.x + threadIdx.x;
    int node = gtid >> 5;
    int lane = gtid & 31;
    if (node >= NN) return;

    const float4* g4 = reinterpret_cast<const float4*>(g_buf);
    size_t base = (size_t)node * 32;
    float4 acc = g4[base + lane];                         // self-loop term
    int e0 = d_rowstart[node];
    int e1 = d_rowstart[node + 1];
    for (int e = e0; e < e1; ++e) {
        int s = d_srcs[e];
        float4 v = g4[(size_t)s * 32 + lane];
        acc.x += v.x; acc.y += v.y; acc.z += v.z; acc.w += v.w;
    }
    float dv  = d_dinv[node];
    float4 bb = reinterpret_cast<const float4*>(bias)[lane];
    float4 xv = reinterpret_cast<const float4*>(x)[base + lane];
    float4 o;
    o.x = fmaf(dv, acc.x, bb.x + xv.x);
    o.y = fmaf(dv, acc.y, bb.y + xv.y);
    o.z = fmaf(dv, acc.z, bb.z + xv.z);
    o.w = fmaf(dv, acc.w, bb.w + xv.w);
    if (relu) {
        o.x = fmaxf(o.x, 0.f); o.y = fmaxf(o.y, 0.f);
        o.z = fmaxf(o.z, 0.f); o.w = fmaxf(o.w, 0.f);
    }
    float4* dst4 = to_out ? reinterpret_cast<float4*>(outp)
                          : reinterpret_cast<float4*>(h_buf);
    dst4[base + lane] = o;
}

// ---------------------------------------------------------------- launch
extern "C" void kernel_launch(void* const* d_in, const int* in_sizes, int n_in,
                              void* d_out, int out_size) {
    const float* x   = (const float*)d_in[0];
    const int*   src = (const int*)  d_in[1];
    const int*   dst = (const int*)  d_in[2];
    const float* W1  = (const float*)d_in[3];
    const float* b1  = (const float*)d_in[4];
    const float* W2  = (const float*)d_in[5];
    const float* b2  = (const float*)d_in[6];
    float* out = (float*)d_out;

    (void)in_sizes; (void)n_in; (void)out_size;

    // CSR build (every call; no caching allowed)
    k_zero_deg<<<(NN + 255) / 256, 256>>>();
    k_count   <<<(EE + 255) / 256, 256>>>(dst);
    k_scan    <<<1, 1024>>>();
    k_scatter <<<(EE + 255) / 256, 256>>>(src, dst);

    const int gemm_grid = (NN + 127) / 128;
    const int agg_grid  = (NN * 32 + 255) / 256;

    // layer 1: h1 = conv(x, W1, b1) + x ; h_buf = relu(h1)
    k_gemm<<<gemm_grid, 256>>>(x, W1);
    k_agg <<<agg_grid, 256>>>(x, b1, out, /*relu=*/1, /*to_out=*/0);

    // layer 2: h2 = conv(h_buf, W2, b2) + x ; h_buf = relu(h2)
    k_gemm<<<gemm_grid, 256>>>(nullptr, W2);
    k_agg <<<agg_grid, 256>>>(x, b2, out, /*relu=*/1, /*to_out=*/0);

    // layer 3: out = conv(h_buf, W2, b2) + x   (no relu)
    k_gemm<<<gemm_grid, 256>>>(nullptr, W2);
    k_agg <<<agg_grid, 256>>>(x, b2, out, /*relu=*/0, /*to_out=*/1);
}

// round 3
// speedup vs baseline: 1.1086x; 1.1086x over previous
#include <cuda_runtime.h>

#define NN 100000
#define EE 1600000
#define HH 128

typedef unsigned long long ull;

// ---- scratch (device globals; allocation inside kernel_launch is forbidden) ----
static __device__ float g_buf[(size_t)NN * HH];   // scaled GEMM output: (h@W)*dinv[row]
static __device__ float h_buf[(size_t)NN * HH];   // layer activations (relu'd)
static __device__ float d_dinv[NN];
static __device__ int   d_deg[NN];
static __device__ int   d_rowstart[NN + 1];
static __device__ int   d_cursor[NN];
static __device__ int   d_srcs[EE];               // edge sources sorted by dst (CSR)

// ---------------------------------------------------------------- f32x2 helpers
__device__ __forceinline__ void fma2(ull& d, ull a, ull b) {
    asm("fma.rn.f32x2 %0, %1, %2, %3;" : "=l"(d) : "l"(a), "l"(b), "l"(d));
}
__device__ __forceinline__ ull dup2(float v) {
    ull r;
    asm("mov.b64 %0, {%1, %1};" : "=l"(r) : "r"(__float_as_uint(v)));
    return r;
}

// ---------------------------------------------------------------- CSR build
__global__ void k_zero_deg() {
    int i = blockIdx.x * blockDim.x + threadIdx.x;
    if (i < NN / 4) reinterpret_cast<int4*>(d_deg)[i] = make_int4(0, 0, 0, 0);
}

__global__ void k_count(const int* __restrict__ dst) {
    int i = blockIdx.x * blockDim.x + threadIdx.x;
    if (i >= EE / 4) return;
    int4 d = reinterpret_cast<const int4*>(dst)[i];
    atomicAdd(&d_deg[d.x], 1);
    atomicAdd(&d_deg[d.y], 1);
    atomicAdd(&d_deg[d.z], 1);
    atomicAdd(&d_deg[d.w], 1);
}

// Single-block shuffle scan: exclusive prefix over d_deg -> row_start, cursor,
// dinv = rsqrt(deg+1). 1024 threads, 4 elements/thread, 4096/chunk.
__global__ void k_scan() {
    __shared__ int warpsum[32];
    int tid  = threadIdx.x;
    int lane = tid & 31;
    int wid  = tid >> 5;
    int running = 0;
    for (int base = 0; base < NN; base += 4096) {
        int gi = base + tid * 4;
        int4 v = make_int4(0, 0, 0, 0);
        if (gi + 3 < NN) {
            v = *reinterpret_cast<const int4*>(&d_deg[gi]);
        } else {
            if (gi     < NN) v.x = d_deg[gi];
            if (gi + 1 < NN) v.y = d_deg[gi + 1];
            if (gi + 2 < NN) v.z = d_deg[gi + 2];
            if (gi + 3 < NN) v.w = d_deg[gi + 3];
        }
        int t = v.x + v.y + v.z + v.w;
        int inc = t;
#pragma unroll
        for (int off = 1; off < 32; off <<= 1) {
            int n = __shfl_up_sync(0xffffffffu, inc, off);
            if (lane >= off) inc += n;
        }
        if (lane == 31) warpsum[wid] = inc;
        __syncthreads();
        if (wid == 0) {
            int w = warpsum[lane];
            int wi = w;
#pragma unroll
            for (int off = 1; off < 32; off <<= 1) {
                int n = __shfl_up_sync(0xffffffffu, wi, off);
                if (lane >= off) wi += n;
            }
            warpsum[lane] = wi;
        }
        __syncthreads();
        int warpoff = (wid > 0) ? warpsum[wid - 1] : 0;
        int excl = running + warpoff + inc - t;
        if (gi < NN) {
            d_rowstart[gi] = excl; d_cursor[gi] = excl;
            d_dinv[gi] = rsqrtf((float)(v.x + 1)); excl += v.x;
        }
        if (gi + 1 < NN) {
            d_rowstart[gi + 1] = excl; d_cursor[gi + 1] = excl;
            d_dinv[gi + 1] = rsqrtf((float)(v.y + 1)); excl += v.y;
        }
        if (gi + 2 < NN) {
            d_rowstart[gi + 2] = excl; d_cursor[gi + 2] = excl;
            d_dinv[gi + 2] = rsqrtf((float)(v.z + 1)); excl += v.z;
        }
        if (gi + 3 < NN) {
            d_rowstart[gi + 3] = excl; d_cursor[gi + 3] = excl;
            d_dinv[gi + 3] = rsqrtf((float)(v.w + 1));
        }
        int tot = warpsum[31];
        __syncthreads();
        running += tot;
    }
    if (tid == 0) d_rowstart[NN] = EE;
}

__global__ void k_scatter(const int* __restrict__ src, const int* __restrict__ dst) {
    int i = blockIdx.x * blockDim.x + threadIdx.x;
    if (i >= EE / 4) return;
    int4 d = reinterpret_cast<const int4*>(dst)[i];
    int4 s = reinterpret_cast<const int4*>(src)[i];
    d_srcs[atomicAdd(&d_cursor[d.x], 1)] = s.x;
    d_srcs[atomicAdd(&d_cursor[d.y], 1)] = s.y;
    d_srcs[atomicAdd(&d_cursor[d.z], 1)] = s.z;
    d_srcs[atomicAdd(&d_cursor[d.w], 1)] = s.w;
}

// ---------------------------------------------------------------- GEMM (f32x2)
// g_buf[row] = (A[row] @ W) * dinv[row].  A = xin if non-null else h_buf.
// Block: 256 threads -> 128 rows x 128 cols tile; thread: 8x8 micro-tile
// organized as 4 row-pairs x 8 cols of packed f32x2 accumulators.
__global__ void __launch_bounds__(256, 2)
k_gemm(const float* __restrict__ xin, const float* __restrict__ W) {
    const float* A = xin ? xin : (const float*)h_buf;
    __shared__ float As[16][128];   // As[k][row]  (A transposed in smem)
    __shared__ float Bs[16][128];   // Bs[k][col]
    int tid  = threadIdx.x;
    int row0 = blockIdx.x * 128;
    int tr = tid >> 4;   // 0..15 -> rows tr*8..tr*8+7
    int tc = tid & 15;   // 0..15 -> cols tc*8..tc*8+7

    ull acc[4][8];       // acc[i2][j]: lo = row 2*i2, hi = row 2*i2+1, col j
#pragma unroll
    for (int i = 0; i < 4; i++)
#pragma unroll
        for (int j = 0; j < 8; j++) acc[i][j] = 0ull;

    for (int kc = 0; kc < HH; kc += 16) {
        // stage A chunk (128 rows x 16 k), transposed into As[k][row]
#pragma unroll
        for (int q = 0; q < 2; q++) {
            int t2 = tid * 2 + q;          // 0..511
            int r  = t2 >> 2;              // 0..127
            int k4 = (t2 & 3) * 4;         // 0,4,8,12
            int grow = row0 + r;
            float4 v = make_float4(0.f, 0.f, 0.f, 0.f);
            if (grow < NN)
                v = *reinterpret_cast<const float4*>(A + (size_t)grow * HH + kc + k4);
            As[k4 + 0][r] = v.x; As[k4 + 1][r] = v.y;
            As[k4 + 2][r] = v.z; As[k4 + 3][r] = v.w;
        }
        // stage B chunk (16 k x 128 cols)
#pragma unroll
        for (int q = 0; q < 2; q++) {
            int t2 = tid * 2 + q;
            int k  = t2 >> 5;              // 0..15
            int j4 = (t2 & 31) * 4;        // 0..124
            *reinterpret_cast<float4*>(&Bs[k][j4]) =
                *reinterpret_cast<const float4*>(W + (size_t)(kc + k) * HH + j4);
        }
        __syncthreads();
#pragma unroll
        for (int k = 0; k < 16; k++) {
            ull a2[4];
            const ull* ap = reinterpret_cast<const ull*>(&As[k][tr * 8]);
            a2[0] = ap[0]; a2[1] = ap[1]; a2[2] = ap[2]; a2[3] = ap[3];
            float b[8];
            *reinterpret_cast<float4*>(&b[0]) = *reinterpret_cast<const float4*>(&Bs[k][tc * 8]);
            *reinterpret_cast<float4*>(&b[4]) = *reinterpret_cast<const float4*>(&Bs[k][tc * 8 + 4]);
            ull bb[8];
#pragma unroll
            for (int j = 0; j < 8; j++) bb[j] = dup2(b[j]);
#pragma unroll
            for (int i = 0; i < 4; i++)
#pragma unroll
                for (int j = 0; j < 8; j++)
                    fma2(acc[i][j], a2[i], bb[j]);
        }
        __syncthreads();
    }
    // epilogue: scale by dinv[row], write g_buf
#pragma unroll
    for (int i2 = 0; i2 < 4; i2++) {
#pragma unroll
        for (int p = 0; p < 2; p++) {
            int grow = row0 + tr * 8 + i2 * 2 + p;
            if (grow < NN) {
                float dv = d_dinv[grow];
                float o[8];
#pragma unroll
                for (int j = 0; j < 8; j++) {
                    float2 v = *reinterpret_cast<float2*>(&acc[i2][j]);
                    o[j] = (p == 0 ? v.x : v.y) * dv;
                }
                *reinterpret_cast<float4*>(&g_buf[(size_t)grow * HH + tc * 8]) =
                    *reinterpret_cast<float4*>(&o[0]);
                *reinterpret_cast<float4*>(&g_buf[(size_t)grow * HH + tc * 8 + 4]) =
                    *reinterpret_cast<float4*>(&o[4]);
            }
        }
    }
}

// ---------------------------------------------------------------- aggregation
// out[i] = dinv[i] * (g[i] + sum_{e in in-edges(i)} g[src_e]) + bias + x[i]
// warp per node; lane handles 4 contiguous cols (float4).
__global__ void k_agg(const float* __restrict__ x, const float* __restrict__ bias,
                      float* __restrict__ outp, int relu, int to_out) {
    int gtid = blockIdx.x * blockDim.x + threadIdx.x;
    int node = gtid >> 5;
    int lane = gtid & 31;
    if (node >= NN) return;

    const float4* g4 = reinterpret_cast<const float4*>(g_buf);
    size_t base = (size_t)node * 32;
    float4 acc = g4[base + lane];                         // self-loop term
    int e0 = d_rowstart[node];
    int e1 = d_rowstart[node + 1];
    for (int e = e0; e < e1; ++e) {
        int s = d_srcs[e];
        float4 v = g4[(size_t)s * 32 + lane];
        acc.x += v.x; acc.y += v.y; acc.z += v.z; acc.w += v.w;
    }
    float dv  = d_dinv[node];
    float4 bb = reinterpret_cast<const float4*>(bias)[lane];
    float4 xv = reinterpret_cast<const float4*>(x)[base + lane];
    float4 o;
    o.x = fmaf(dv, acc.x, bb.x + xv.x);
    o.y = fmaf(dv, acc.y, bb.y + xv.y);
    o.z = fmaf(dv, acc.z, bb.z + xv.z);
    o.w = fmaf(dv, acc.w, bb.w + xv.w);
    if (relu) {
        o.x = fmaxf(o.x, 0.f); o.y = fmaxf(o.y, 0.f);
        o.z = fmaxf(o.z, 0.f); o.w = fmaxf(o.w, 0.f);
    }
    float4* dst4 = to_out ? reinterpret_cast<float4*>(outp)
                          : reinterpret_cast<float4*>(h_buf);
    dst4[base + lane] = o;
}

// ---------------------------------------------------------------- launch
extern "C" void kernel_launch(void* const* d_in, const int* in_sizes, int n_in,
                              void* d_out, int out_size) {
    const float* x   = (const float*)d_in[0];
    const int*   src = (const int*)  d_in[1];
    const int*   dst = (const int*)  d_in[2];
    const float* W1  = (const float*)d_in[3];
    const float* b1  = (const float*)d_in[4];
    const float* W2  = (const float*)d_in[5];
    const float* b2  = (const float*)d_in[6];
    float* out = (float*)d_out;

    (void)in_sizes; (void)n_in; (void)out_size;

    // CSR build (every call; no caching allowed)
    k_zero_deg<<<(NN / 4 + 255) / 256, 256>>>();
    k_count   <<<(EE / 4 + 255) / 256, 256>>>(dst);
    k_scan    <<<1, 1024>>>();
    k_scatter <<<(EE / 4 + 255) / 256, 256>>>(src, dst);

    const int gemm_grid = (NN + 127) / 128;
    const int agg_grid  = (NN * 32 + 255) / 256;

    // layer 1: h1 = conv(x, W1, b1) + x ; h_buf = relu(h1)
    k_gemm<<<gemm_grid, 256>>>(x, W1);
    k_agg <<<agg_grid, 256>>>(x, b1, out, /*relu=*/1, /*to_out=*/0);

    // layer 2: h2 = conv(h_buf, W2, b2) + x ; h_buf = relu(h2)
    k_gemm<<<gemm_grid, 256>>>(nullptr, W2);
    k_agg <<<agg_grid, 256>>>(x, b2, out, /*relu=*/1, /*to_out=*/0);

    // layer 3: out = conv(h_buf, W2, b2) + x   (no relu)
    k_gemm<<<gemm_grid, 256>>>(nullptr, W2);
    k_agg <<<agg_grid, 256>>>(x, b2, out, /*relu=*/0, /*to_out=*/1);
}

// round 5
// speedup vs baseline: 1.1087x; 1.0001x over previous
#include <cuda_runtime.h>
#include <cuda_bf16.h>
#include <cstdint>

#define NN 100000
#define EE 1600000
#define HH 128

typedef unsigned long long ull;

// ---- scratch (device globals; allocation inside kernel_launch is forbidden) ----
static __device__ float g_buf[(size_t)NN * HH];   // scaled GEMM output: (h@W)*dinv[row]
static __device__ float h_buf[(size_t)NN * HH];   // layer activations (relu'd)
static __device__ float d_dinv[NN];
static __device__ int   d_deg[NN];
static __device__ int   d_rowstart[NN + 1];
static __device__ int   d_cursor[NN];
static __device__ int   d_srcs[EE];               // edge sources sorted by dst (CSR)

// ---------------------------------------------------------------- CSR build
__global__ void k_zero_deg() {
    int i = blockIdx.x * blockDim.x + threadIdx.x;
    if (i < NN / 4) reinterpret_cast<int4*>(d_deg)[i] = make_int4(0, 0, 0, 0);
}

__global__ void k_count(const int* __restrict__ dst) {
    int i = blockIdx.x * blockDim.x + threadIdx.x;
    if (i >= EE / 4) return;
    int4 d = reinterpret_cast<const int4*>(dst)[i];
    atomicAdd(&d_deg[d.x], 1);
    atomicAdd(&d_deg[d.y], 1);
    atomicAdd(&d_deg[d.z], 1);
    atomicAdd(&d_deg[d.w], 1);
}

// Single-block shuffle scan: exclusive prefix over d_deg -> row_start, cursor,
// dinv = rsqrt(deg+1). 1024 threads, 4 elements/thread, 4096/chunk.
__global__ void k_scan() {
    __shared__ int warpsum[32];
    int tid  = threadIdx.x;
    int lane = tid & 31;
    int wid  = tid >> 5;
    int running = 0;
    for (int base = 0; base < NN; base += 4096) {
        int gi = base + tid * 4;
        int4 v = make_int4(0, 0, 0, 0);
        if (gi + 3 < NN) {
            v = *reinterpret_cast<const int4*>(&d_deg[gi]);
        } else {
            if (gi     < NN) v.x = d_deg[gi];
            if (gi + 1 < NN) v.y = d_deg[gi + 1];
            if (gi + 2 < NN) v.z = d_deg[gi + 2];
            if (gi + 3 < NN) v.w = d_deg[gi + 3];
        }
        int t = v.x + v.y + v.z + v.w;
        int inc = t;
#pragma unroll
        for (int off = 1; off < 32; off <<= 1) {
            int n = __shfl_up_sync(0xffffffffu, inc, off);
            if (lane >= off) inc += n;
        }
        if (lane == 31) warpsum[wid] = inc;
        __syncthreads();
        if (wid == 0) {
            int w = warpsum[lane];
            int wi = w;
#pragma unroll
            for (int off = 1; off < 32; off <<= 1) {
                int n = __shfl_up_sync(0xffffffffu, wi, off);
                if (lane >= off) wi += n;
            }
            warpsum[lane] = wi;
        }
        __syncthreads();
        int warpoff = (wid > 0) ? warpsum[wid - 1] : 0;
        int excl = running + warpoff + inc - t;
        if (gi < NN) {
            d_rowstart[gi] = excl; d_cursor[gi] = excl;
            d_dinv[gi] = rsqrtf((float)(v.x + 1)); excl += v.x;
        }
        if (gi + 1 < NN) {
            d_rowstart[gi + 1] = excl; d_cursor[gi + 1] = excl;
            d_dinv[gi + 1] = rsqrtf((float)(v.y + 1)); excl += v.y;
        }
        if (gi + 2 < NN) {
            d_rowstart[gi + 2] = excl; d_cursor[gi + 2] = excl;
            d_dinv[gi + 2] = rsqrtf((float)(v.z + 1)); excl += v.z;
        }
        if (gi + 3 < NN) {
            d_rowstart[gi + 3] = excl; d_cursor[gi + 3] = excl;
            d_dinv[gi + 3] = rsqrtf((float)(v.w + 1));
        }
        int tot = warpsum[31];
        __syncthreads();
        running += tot;
    }
    if (tid == 0) d_rowstart[NN] = EE;
}

__global__ void k_scatter(const int* __restrict__ src, const int* __restrict__ dst) {
    int i = blockIdx.x * blockDim.x + threadIdx.x;
    if (i >= EE / 4) return;
    int4 d = reinterpret_cast<const int4*>(dst)[i];
    int4 s = reinterpret_cast<const int4*>(src)[i];
    d_srcs[atomicAdd(&d_cursor[d.x], 1)] = s.x;
    d_srcs[atomicAdd(&d_cursor[d.y], 1)] = s.y;
    d_srcs[atomicAdd(&d_cursor[d.z], 1)] = s.z;
    d_srcs[atomicAdd(&d_cursor[d.w], 1)] = s.w;
}

// ---------------------------------------------------------------- mma.sync GEMM
// g_buf[row] = (A[row] @ W) * dinv[row].
// bf16 3-term split: D = Ah@Wh + Al@Wh + Ah@Wl  (fp32 accumulate).
// CTA: 128 rows x 128 cols, 8 warps x 16 rows. Smem tiles padded to LDA=136.

#define LDA 136
#define TILE_B (128 * LDA * 2)       // 34816 bytes per tile
#define SM_AH 0
#define SM_AL (TILE_B)
#define SM_BH (2 * TILE_B)
#define SM_BL (3 * TILE_B)
#define SM_TOTAL (4 * TILE_B)        // 139264

__device__ __forceinline__ uint32_t smem_u32(const void* p) {
    uint32_t a;
    asm("{ .reg .u64 t; cvta.to.shared.u64 t, %1; cvt.u32.u64 %0, t; }" : "=r"(a) : "l"(p));
    return a;
}
__device__ __forceinline__ void ldsm4(uint32_t* r, uint32_t addr) {
    asm volatile("ldmatrix.sync.aligned.m8n8.x4.shared.b16 {%0,%1,%2,%3}, [%4];"
                 : "=r"(r[0]), "=r"(r[1]), "=r"(r[2]), "=r"(r[3]) : "r"(addr));
}
__device__ __forceinline__ void mma_bf16(float* d, const uint32_t* a, const uint32_t* b) {
    asm volatile(
        "mma.sync.aligned.m16n8k16.row.col.f32.bf16.bf16.f32 "
        "{%0,%1,%2,%3}, {%4,%5,%6,%7}, {%8,%9}, {%0,%1,%2,%3};"
        : "+f"(d[0]), "+f"(d[1]), "+f"(d[2]), "+f"(d[3])
        : "r"(a[0]), "r"(a[1]), "r"(a[2]), "r"(a[3]), "r"(b[0]), "r"(b[1]));
}
__device__ __forceinline__ uint32_t pack_hi(float x, float y, uint32_t& lo) {
    __nv_bfloat16 h0 = __float2bfloat16_rn(x);
    __nv_bfloat16 h1 = __float2bfloat16_rn(y);
    __nv_bfloat16 l0 = __float2bfloat16_rn(x - __bfloat162float(h0));
    __nv_bfloat16 l1 = __float2bfloat16_rn(y - __bfloat162float(h1));
    lo = (uint32_t)__bfloat16_as_ushort(l0) | ((uint32_t)__bfloat16_as_ushort(l1) << 16);
    return (uint32_t)__bfloat16_as_ushort(h0) | ((uint32_t)__bfloat16_as_ushort(h1) << 16);
}

__global__ void __launch_bounds__(256, 1)
k_gemm_mma(const float* __restrict__ xin, const float* __restrict__ W) {
    extern __shared__ __align__(16) char smem[];
    const float* A = xin ? xin : (const float*)h_buf;
    uint32_t sb = smem_u32(smem);
    int tid  = threadIdx.x;
    int wid  = tid >> 5;
    int lane = tid & 31;
    int row0 = blockIdx.x * 128;

    // ---- stage A rows (fp32 -> bf16 hi/lo), padded row-major [r][k] ----
    for (int idx = tid; idx < 128 * 64; idx += 256) {
        int r  = idx >> 6;
        int kp = idx & 63;                 // k-pair 2kp, 2kp+1
        int grow = row0 + r;
        float2 v = make_float2(0.f, 0.f);
        if (grow < NN)
            v = *reinterpret_cast<const float2*>(A + (size_t)grow * HH + kp * 2);
        uint32_t lo, hi = pack_hi(v.x, v.y, lo);
        uint32_t off = (uint32_t)(r * LDA + kp * 2) * 2;
        *reinterpret_cast<uint32_t*>(smem + SM_AH + off) = hi;
        *reinterpret_cast<uint32_t*>(smem + SM_AL + off) = lo;
    }
    // ---- stage W transposed: Bt[n][k] = W[k][n], bf16 hi/lo ----
    for (int idx = tid; idx < 128 * 64; idx += 256) {
        int k = idx >> 6;
        int n = (idx & 63) * 2;            // coalesced fp32x2 read along n
        float2 v = *reinterpret_cast<const float2*>(W + (size_t)k * HH + n);
        __nv_bfloat16 h0 = __float2bfloat16_rn(v.x);
        __nv_bfloat16 h1 = __float2bfloat16_rn(v.y);
        __nv_bfloat16 l0 = __float2bfloat16_rn(v.x - __bfloat162float(h0));
        __nv_bfloat16 l1 = __float2bfloat16_rn(v.y - __bfloat162float(h1));
        uint32_t o0 = (uint32_t)(n * LDA + k) * 2;
        uint32_t o1 = (uint32_t)((n + 1) * LDA + k) * 2;
        *reinterpret_cast<__nv_bfloat16*>(smem + SM_BH + o0) = h0;
        *reinterpret_cast<__nv_bfloat16*>(smem + SM_BH + o1) = h1;
        *reinterpret_cast<__nv_bfloat16*>(smem + SM_BL + o0) = l0;
        *reinterpret_cast<__nv_bfloat16*>(smem + SM_BL + o1) = l1;
    }
    __syncthreads();

    // ---- warp-level mma: warp wid handles rows m0..m0+15, all 128 cols ----
    int m0 = wid * 16;
    float acc[16][4];
#pragma unroll
    for (int i = 0; i < 16; i++)
#pragma unroll
        for (int j = 0; j < 4; j++) acc[i][j] = 0.f;

    // ldmatrix lane address offsets
    uint32_t a_off = (uint32_t)((m0 + (lane & 15)) * LDA + ((lane >> 4) << 3)) * 2;
    uint32_t b_off = (uint32_t)(((lane & 7) + ((lane >> 1) & 8)) * LDA + (lane & 8)) * 2;

#pragma unroll
    for (int ks = 0; ks < 8; ks++) {
        int k0 = ks * 16;
        uint32_t ah[4], al[4];
        ldsm4(ah, sb + SM_AH + a_off + k0 * 2);
        ldsm4(al, sb + SM_AL + a_off + k0 * 2);
#pragma unroll
        for (int np = 0; np < 8; np++) {           // n-pair: tiles 2np, 2np+1
            uint32_t bh[4], bl[4];
            uint32_t bo = (uint32_t)((np * 16) * LDA + k0) * 2 + b_off;
            ldsm4(bh, sb + SM_BH + bo);
            ldsm4(bl, sb + SM_BL + bo);
            mma_bf16(acc[2 * np],     ah, bh);
            mma_bf16(acc[2 * np + 1], ah, bh + 2);
            mma_bf16(acc[2 * np],     al, bh);
            mma_bf16(acc[2 * np + 1], al, bh + 2);
            mma_bf16(acc[2 * np],     ah, bl);
            mma_bf16(acc[2 * np + 1], ah, bl + 2);
        }
    }

    // ---- epilogue: scale by dinv[row], store to g_buf ----
    int r0 = row0 + m0 + (lane >> 2);
    int r1 = r0 + 8;
    float dv0 = (r0 < NN) ? d_dinv[r0] : 0.f;
    float dv1 = (r1 < NN) ? d_dinv[r1] : 0.f;
    int c0 = (lane & 3) * 2;
#pragma unroll
    for (int nt = 0; nt < 16; nt++) {
        int col = nt * 8 + c0;
        if (r0 < NN) {
            float2 o = make_float2(acc[nt][0] * dv0, acc[nt][1] * dv0);
            *reinterpret_cast<float2*>(&g_buf[(size_t)r0 * HH + col]) = o;
        }
        if (r1 < NN) {
            float2 o = make_float2(acc[nt][2] * dv1, acc[nt][3] * dv1);
            *reinterpret_cast<float2*>(&g_buf[(size_t)r1 * HH + col]) = o;
        }
    }
}

// ---------------------------------------------------------------- aggregation
// out[i] = dinv[i] * (g[i] + sum_{e in in-edges(i)} g[src_e]) + bias + x[i]
__global__ void k_agg(const float* __restrict__ x, const float* __restrict__ bias,
                      float* __restrict__ outp, int relu, int to_out) {
    int gtid = blockIdx.x * blockDim.x + threadIdx.x;
    int node = gtid >> 5;
    int lane = gtid & 31;
    if (node >= NN) return;

    const float4* g4 = reinterpret_cast<const float4*>(g_buf);
    size_t base = (size_t)node * 32;
    float4 acc = g4[base + lane];                         // self-loop term
    int e0 = d_rowstart[node];
    int e1 = d_rowstart[node + 1];
    for (int e = e0; e < e1; ++e) {
        int s = d_srcs[e];
        float4 v = g4[(size_t)s * 32 + lane];
        acc.x += v.x; acc.y += v.y; acc.z += v.z; acc.w += v.w;
    }
    float dv  = d_dinv[node];
    float4 bb = reinterpret_cast<const float4*>(bias)[lane];
    float4 xv = reinterpret_cast<const float4*>(x)[base + lane];
    float4 o;
    o.x = fmaf(dv, acc.x, bb.x + xv.x);
    o.y = fmaf(dv, acc.y, bb.y + xv.y);
    o.z = fmaf(dv, acc.z, bb.z + xv.z);
    o.w = fmaf(dv, acc.w, bb.w + xv.w);
    if (relu) {
        o.x = fmaxf(o.x, 0.f); o.y = fmaxf(o.y, 0.f);
        o.z = fmaxf(o.z, 0.f); o.w = fmaxf(o.w, 0.f);
    }
    float4* dst4 = to_out ? reinterpret_cast<float4*>(outp)
                          : reinterpret_cast<float4*>(h_buf);
    dst4[base + lane] = o;
}

// ---------------------------------------------------------------- launch
extern "C" void kernel_launch(void* const* d_in, const int* in_sizes, int n_in,
                              void* d_out, int out_size) {
    const float* x   = (const float*)d_in[0];
    const int*   src = (const int*)  d_in[1];
    const int*   dst = (const int*)  d_in[2];
    const float* W1  = (const float*)d_in[3];
    const float* b1  = (const float*)d_in[4];
    const float* W2  = (const float*)d_in[5];
    const float* b2  = (const float*)d_in[6];
    float* out = (float*)d_out;

    (void)in_sizes; (void)n_in; (void)out_size;

    static int smem_set = 0;
    if (!smem_set) {
        cudaFuncSetAttribute(k_gemm_mma, cudaFuncAttributeMaxDynamicSharedMemorySize, SM_TOTAL);
        smem_set = 1;
    }

    // CSR build (every call; no caching allowed)
    k_zero_deg<<<(NN / 4 + 255) / 256, 256>>>();
    k_count   <<<(EE / 4 + 255) / 256, 256>>>(dst);
    k_scan    <<<1, 1024>>>();
    k_scatter <<<(EE / 4 + 255) / 256, 256>>>(src, dst);

    const int gemm_grid = (NN + 127) / 128;   // 782
    const int agg_grid  = (NN * 32 + 255) / 256;

    // layer 1: h1 = conv(x, W1, b1) + x ; h_buf = relu(h1)
    k_gemm_mma<<<gemm_grid, 256, SM_TOTAL>>>(x, W1);
    k_agg <<<agg_grid, 256>>>(x, b1, out, /*relu=*/1, /*to_out=*/0);

    // layer 2: h2 = conv(h_buf, W2, b2) + x ; h_buf = relu(h2)
    k_gemm_mma<<<gemm_grid, 256, SM_TOTAL>>>(nullptr, W2);
    k_agg <<<agg_grid, 256>>>(x, b2, out, /*relu=*/1, /*to_out=*/0);

    // layer 3: out = conv(h_buf, W2, b2) + x   (no relu)
    k_gemm_mma<<<gemm_grid, 256, SM_TOTAL>>>(nullptr, W2);
    k_agg <<<agg_grid, 256>>>(x, b2, out, /*relu=*/0, /*to_out=*/1);
}

// round 6
// speedup vs baseline: 1.1861x; 1.0698x over previous
#include <cuda_runtime.h>
#include <cuda_bf16.h>
#include <cuda_fp16.h>
#include <cstdint>

#define NN 100000
#define EE 1600000
#define HH 128

typedef unsigned long long ull;

// ---- scratch (device globals; allocation inside kernel_launch is forbidden) ----
static __device__ __half g_hb[(size_t)NN * HH];   // UNSCALED GEMM output (h@W), fp16
static __device__ float  h_buf[(size_t)NN * HH];  // layer activations (relu'd), fp32
static __device__ float  d_dinv[NN];
static __device__ int    d_deg[NN];
static __device__ int    d_rowstart[NN + 1];
static __device__ int    d_cursor[NN];
static __device__ int    d_srcs[EE];              // edge sources sorted by dst (CSR)

// ---------------------------------------------------------------- CSR build
__global__ void k_zero_deg() {
    int i = blockIdx.x * blockDim.x + threadIdx.x;
    if (i < NN / 4) reinterpret_cast<int4*>(d_deg)[i] = make_int4(0, 0, 0, 0);
}

__global__ void k_count(const int* __restrict__ dst) {
    int i = blockIdx.x * blockDim.x + threadIdx.x;
    if (i >= EE / 4) return;
    int4 d = reinterpret_cast<const int4*>(dst)[i];
    atomicAdd(&d_deg[d.x], 1);
    atomicAdd(&d_deg[d.y], 1);
    atomicAdd(&d_deg[d.z], 1);
    atomicAdd(&d_deg[d.w], 1);
}

// Single-block shuffle scan: exclusive prefix over d_deg -> row_start, cursor,
// dinv = rsqrt(deg+1).
__global__ void k_scan() {
    __shared__ int warpsum[32];
    int tid  = threadIdx.x;
    int lane = tid & 31;
    int wid  = tid >> 5;
    int running = 0;
    for (int base = 0; base < NN; base += 4096) {
        int gi = base + tid * 4;
        int4 v = make_int4(0, 0, 0, 0);
        if (gi + 3 < NN) {
            v = *reinterpret_cast<const int4*>(&d_deg[gi]);
        } else {
            if (gi     < NN) v.x = d_deg[gi];
            if (gi + 1 < NN) v.y = d_deg[gi + 1];
            if (gi + 2 < NN) v.z = d_deg[gi + 2];
            if (gi + 3 < NN) v.w = d_deg[gi + 3];
        }
        int t = v.x + v.y + v.z + v.w;
        int inc = t;
#pragma unroll
        for (int off = 1; off < 32; off <<= 1) {
            int n = __shfl_up_sync(0xffffffffu, inc, off);
            if (lane >= off) inc += n;
        }
        if (lane == 31) warpsum[wid] = inc;
        __syncthreads();
        if (wid == 0) {
            int wi = warpsum[lane];
#pragma unroll
            for (int off = 1; off < 32; off <<= 1) {
                int n = __shfl_up_sync(0xffffffffu, wi, off);
                if (lane >= off) wi += n;
            }
            warpsum[lane] = wi;
        }
        __syncthreads();
        int warpoff = (wid > 0) ? warpsum[wid - 1] : 0;
        int excl = running + warpoff + inc - t;
        if (gi < NN) {
            d_rowstart[gi] = excl; d_cursor[gi] = excl;
            d_dinv[gi] = rsqrtf((float)(v.x + 1)); excl += v.x;
        }
        if (gi + 1 < NN) {
            d_rowstart[gi + 1] = excl; d_cursor[gi + 1] = excl;
            d_dinv[gi + 1] = rsqrtf((float)(v.y + 1)); excl += v.y;
        }
        if (gi + 2 < NN) {
            d_rowstart[gi + 2] = excl; d_cursor[gi + 2] = excl;
            d_dinv[gi + 2] = rsqrtf((float)(v.z + 1)); excl += v.z;
        }
        if (gi + 3 < NN) {
            d_rowstart[gi + 3] = excl; d_cursor[gi + 3] = excl;
            d_dinv[gi + 3] = rsqrtf((float)(v.w + 1));
        }
        int tot = warpsum[31];
        __syncthreads();
        running += tot;
    }
    if (tid == 0) d_rowstart[NN] = EE;
}

__global__ void k_scatter(const int* __restrict__ src, const int* __restrict__ dst) {
    int i = blockIdx.x * blockDim.x + threadIdx.x;
    if (i >= EE / 4) return;
    int4 d = reinterpret_cast<const int4*>(dst)[i];
    int4 s = reinterpret_cast<const int4*>(src)[i];
    d_srcs[atomicAdd(&d_cursor[d.x], 1)] = s.x;
    d_srcs[atomicAdd(&d_cursor[d.y], 1)] = s.y;
    d_srcs[atomicAdd(&d_cursor[d.z], 1)] = s.z;
    d_srcs[atomicAdd(&d_cursor[d.w], 1)] = s.w;
}

// ---------------------------------------------------------------- mma.sync GEMM
// g_hb[row] = A[row] @ W   (fp16 out, NO dinv scaling — applied in agg).
// bf16 3-term split: D = Ah@Wh + Al@Wh + Ah@Wl  (fp32 accumulate).

#define LDA 136
#define TILE_B (128 * LDA * 2)
#define SM_AH 0
#define SM_AL (TILE_B)
#define SM_BH (2 * TILE_B)
#define SM_BL (3 * TILE_B)
#define SM_TOTAL (4 * TILE_B)        // 139264

__device__ __forceinline__ uint32_t smem_u32(const void* p) {
    uint32_t a;
    asm("{ .reg .u64 t; cvta.to.shared.u64 t, %1; cvt.u32.u64 %0, t; }" : "=r"(a) : "l"(p));
    return a;
}
__device__ __forceinline__ void ldsm4(uint32_t* r, uint32_t addr) {
    asm volatile("ldmatrix.sync.aligned.m8n8.x4.shared.b16 {%0,%1,%2,%3}, [%4];"
                 : "=r"(r[0]), "=r"(r[1]), "=r"(r[2]), "=r"(r[3]) : "r"(addr));
}
__device__ __forceinline__ void mma_bf16(float* d, const uint32_t* a, const uint32_t* b) {
    asm volatile(
        "mma.sync.aligned.m16n8k16.row.col.f32.bf16.bf16.f32 "
        "{%0,%1,%2,%3}, {%4,%5,%6,%7}, {%8,%9}, {%0,%1,%2,%3};"
        : "+f"(d[0]), "+f"(d[1]), "+f"(d[2]), "+f"(d[3])
        : "r"(a[0]), "r"(a[1]), "r"(a[2]), "r"(a[3]), "r"(b[0]), "r"(b[1]));
}
__device__ __forceinline__ uint32_t pack_hi(float x, float y, uint32_t& lo) {
    __nv_bfloat16 h0 = __float2bfloat16_rn(x);
    __nv_bfloat16 h1 = __float2bfloat16_rn(y);
    __nv_bfloat16 l0 = __float2bfloat16_rn(x - __bfloat162float(h0));
    __nv_bfloat16 l1 = __float2bfloat16_rn(y - __bfloat162float(h1));
    lo = (uint32_t)__bfloat16_as_ushort(l0) | ((uint32_t)__bfloat16_as_ushort(l1) << 16);
    return (uint32_t)__bfloat16_as_ushort(h0) | ((uint32_t)__bfloat16_as_ushort(h1) << 16);
}

__global__ void __launch_bounds__(256, 1)
k_gemm_mma(const float* __restrict__ xin, const float* __restrict__ W) {
    extern __shared__ __align__(16) char smem[];
    const float* A = xin ? xin : (const float*)h_buf;
    uint32_t sb = smem_u32(smem);
    int tid  = threadIdx.x;
    int wid  = tid >> 5;
    int lane = tid & 31;
    int row0 = blockIdx.x * 128;

    // ---- stage A rows (fp32 -> bf16 hi/lo), padded row-major [r][k] ----
    for (int idx = tid; idx < 128 * 64; idx += 256) {
        int r  = idx >> 6;
        int kp = idx & 63;
        int grow = row0 + r;
        float2 v = make_float2(0.f, 0.f);
        if (grow < NN)
            v = *reinterpret_cast<const float2*>(A + (size_t)grow * HH + kp * 2);
        uint32_t lo, hi = pack_hi(v.x, v.y, lo);
        uint32_t off = (uint32_t)(r * LDA + kp * 2) * 2;
        *reinterpret_cast<uint32_t*>(smem + SM_AH + off) = hi;
        *reinterpret_cast<uint32_t*>(smem + SM_AL + off) = lo;
    }
    // ---- stage W transposed: Bt[n][k] = W[k][n], bf16 hi/lo ----
    for (int idx = tid; idx < 128 * 64; idx += 256) {
        int k = idx >> 6;
        int n = (idx & 63) * 2;
        float2 v = *reinterpret_cast<const float2*>(W + (size_t)k * HH + n);
        __nv_bfloat16 h0 = __float2bfloat16_rn(v.x);
        __nv_bfloat16 h1 = __float2bfloat16_rn(v.y);
        __nv_bfloat16 l0 = __float2bfloat16_rn(v.x - __bfloat162float(h0));
        __nv_bfloat16 l1 = __float2bfloat16_rn(v.y - __bfloat162float(h1));
        uint32_t o0 = (uint32_t)(n * LDA + k) * 2;
        uint32_t o1 = (uint32_t)((n + 1) * LDA + k) * 2;
        *reinterpret_cast<__nv_bfloat16*>(smem + SM_BH + o0) = h0;
        *reinterpret_cast<__nv_bfloat16*>(smem + SM_BH + o1) = h1;
        *reinterpret_cast<__nv_bfloat16*>(smem + SM_BL + o0) = l0;
        *reinterpret_cast<__nv_bfloat16*>(smem + SM_BL + o1) = l1;
    }
    __syncthreads();

    int m0 = wid * 16;
    float acc[16][4];
#pragma unroll
    for (int i = 0; i < 16; i++)
#pragma unroll
        for (int j = 0; j < 4; j++) acc[i][j] = 0.f;

    uint32_t a_off = (uint32_t)((m0 + (lane & 15)) * LDA + ((lane >> 4) << 3)) * 2;
    uint32_t b_off = (uint32_t)(((lane & 7) + ((lane >> 1) & 8)) * LDA + (lane & 8)) * 2;

#pragma unroll
    for (int ks = 0; ks < 8; ks++) {
        int k0 = ks * 16;
        uint32_t ah[4], al[4];
        ldsm4(ah, sb + SM_AH + a_off + k0 * 2);
        ldsm4(al, sb + SM_AL + a_off + k0 * 2);
#pragma unroll
        for (int np = 0; np < 8; np++) {
            uint32_t bh[4], bl[4];
            uint32_t bo = (uint32_t)((np * 16) * LDA + k0) * 2 + b_off;
            ldsm4(bh, sb + SM_BH + bo);
            ldsm4(bl, sb + SM_BL + bo);
            mma_bf16(acc[2 * np],     ah, bh);
            mma_bf16(acc[2 * np + 1], ah, bh + 2);
            mma_bf16(acc[2 * np],     al, bh);
            mma_bf16(acc[2 * np + 1], al, bh + 2);
            mma_bf16(acc[2 * np],     ah, bl);
            mma_bf16(acc[2 * np + 1], ah, bl + 2);
        }
    }

    // ---- epilogue: store fp16, unscaled ----
    int r0 = row0 + m0 + (lane >> 2);
    int r1 = r0 + 8;
    int c0 = (lane & 3) * 2;
#pragma unroll
    for (int nt = 0; nt < 16; nt++) {
        int col = nt * 8 + c0;
        if (r0 < NN)
            *reinterpret_cast<__half2*>(&g_hb[(size_t)r0 * HH + col]) =
                __floats2half2_rn(acc[nt][0], acc[nt][1]);
        if (r1 < NN)
            *reinterpret_cast<__half2*>(&g_hb[(size_t)r1 * HH + col]) =
                __floats2half2_rn(acc[nt][2], acc[nt][3]);
    }
}

// ---------------------------------------------------------------- aggregation
// out[i] = dinv[i]*( dinv[i]*g[i] + sum_e dinv[src_e]*g[src_e] ) + bias + x[i]
// warp per node; lane handles 4 cols (uint2 of 4 halves = 8B).
__global__ void k_agg(const float* __restrict__ x, const float* __restrict__ bias,
                      float* __restrict__ outp, int relu, int to_out) {
    int gtid = blockIdx.x * blockDim.x + threadIdx.x;
    int node = gtid >> 5;
    int lane = gtid & 31;
    if (node >= NN) return;

    const uint2* g2 = reinterpret_cast<const uint2*>(g_hb);   // [node*32 + lane]
    size_t base = (size_t)node * 32;
    float dv = d_dinv[node];

    uint2 sv = g2[base + lane];
    __half2 p0 = *reinterpret_cast<__half2*>(&sv.x);
    __half2 p1 = *reinterpret_cast<__half2*>(&sv.y);
    float2 f0 = __half22float2(p0);
    float2 f1 = __half22float2(p1);
    float4 acc = make_float4(f0.x * dv, f0.y * dv, f1.x * dv, f1.y * dv);

    int e0 = d_rowstart[node];
    int e1 = d_rowstart[node + 1];
    for (int e = e0; e < e1; ++e) {
        int s = d_srcs[e];
        float ds = d_dinv[s];
        uint2 v = g2[(size_t)s * 32 + lane];
        __half2 q0 = *reinterpret_cast<__half2*>(&v.x);
        __half2 q1 = *reinterpret_cast<__half2*>(&v.y);
        float2 g0 = __half22float2(q0);
        float2 g1 = __half22float2(q1);
        acc.x = fmaf(ds, g0.x, acc.x);
        acc.y = fmaf(ds, g0.y, acc.y);
        acc.z = fmaf(ds, g1.x, acc.z);
        acc.w = fmaf(ds, g1.y, acc.w);
    }
    size_t cbase = (size_t)node * HH + lane * 4;
    float4 bb = *reinterpret_cast<const float4*>(bias + lane * 4);
    float4 xv = *reinterpret_cast<const float4*>(x + cbase);
    float4 o;
    o.x = fmaf(dv, acc.x, bb.x + xv.x);
    o.y = fmaf(dv, acc.y, bb.y + xv.y);
    o.z = fmaf(dv, acc.z, bb.z + xv.z);
    o.w = fmaf(dv, acc.w, bb.w + xv.w);
    if (relu) {
        o.x = fmaxf(o.x, 0.f); o.y = fmaxf(o.y, 0.f);
        o.z = fmaxf(o.z, 0.f); o.w = fmaxf(o.w, 0.f);
    }
    float* dstp = to_out ? outp : (float*)h_buf;
    *reinterpret_cast<float4*>(dstp + cbase) = o;
}

// ---------------------------------------------------------------- launch
extern "C" void kernel_launch(void* const* d_in, const int* in_sizes, int n_in,
                              void* d_out, int out_size) {
    const float* x   = (const float*)d_in[0];
    const int*   src = (const int*)  d_in[1];
    const int*   dst = (const int*)  d_in[2];
    const float* W1  = (const float*)d_in[3];
    const float* b1  = (const float*)d_in[4];
    const float* W2  = (const float*)d_in[5];
    const float* b2  = (const float*)d_in[6];
    float* out = (float*)d_out;

    (void)in_sizes; (void)n_in; (void)out_size;

    static int inited = 0;
    static cudaStream_t s1;
    static cudaEvent_t evFork, evJoin;
    if (!inited) {
        cudaFuncSetAttribute(k_gemm_mma, cudaFuncAttributeMaxDynamicSharedMemorySize, SM_TOTAL);
        cudaStreamCreateWithFlags(&s1, cudaStreamNonBlocking);
        cudaEventCreateWithFlags(&evFork, cudaEventDisableTiming);
        cudaEventCreateWithFlags(&evJoin, cudaEventDisableTiming);
        inited = 1;
    }

    const int gemm_grid = (NN + 127) / 128;
    const int agg_grid  = (NN * 32 + 255) / 256;

    // Fork: CSR build on s1, GEMM1 on main stream (independent — no dinv in GEMM).
    cudaEventRecord(evFork, 0);
    cudaStreamWaitEvent(s1, evFork, 0);

    k_zero_deg<<<(NN / 4 + 255) / 256, 256, 0, s1>>>();
    k_count   <<<(EE / 4 + 255) / 256, 256, 0, s1>>>(dst);
    k_scan    <<<1, 1024, 0, s1>>>();
    k_scatter <<<(EE / 4 + 255) / 256, 256, 0, s1>>>(src, dst);
    cudaEventRecord(evJoin, s1);

    k_gemm_mma<<<gemm_grid, 256, SM_TOTAL>>>(x, W1);   // overlaps CSR build

    cudaStreamWaitEvent(0, evJoin, 0);                 // join before first agg

    // layer 1
    k_agg<<<agg_grid, 256>>>(x, b1, out, /*relu=*/1, /*to_out=*/0);
    // layer 2
    k_gemm_mma<<<gemm_grid, 256, SM_TOTAL>>>(nullptr, W2);
    k_agg<<<agg_grid, 256>>>(x, b2, out, /*relu=*/1, /*to_out=*/0);
    // layer 3
    k_gemm_mma<<<gemm_grid, 256, SM_TOTAL>>>(nullptr, W2);
    k_agg<<<agg_grid, 256>>>(x, b2, out, /*relu=*/0, /*to_out=*/1);
}

// round 7
// speedup vs baseline: 1.2780x; 1.0775x over previous
#include <cuda_runtime.h>
#include <cuda_bf16.h>
#include <cuda_fp16.h>
#include <cstdint>

#define NN 100000
#define EE 1600000
#define HH 128

typedef unsigned long long ull;

// ---- scratch (device globals) ----
static __device__ __half g_hb[(size_t)NN * HH];   // GEMM output, fp16 (see scale flag)
static __device__ float  h_buf[(size_t)NN * HH];  // layer activations (relu'd), fp32
static __device__ float  d_dinv[NN];
static __device__ int    d_deg[NN];
static __device__ int    d_rowstart[NN + 1];
static __device__ int    d_cursor[NN];
static __device__ int    d_srcs[EE];
// pre-converted W (transposed [n][k], padded LDA=136), bf16 hi/lo
#define LDA 136
static __device__ __nv_bfloat16 d_W1h[128 * LDA], d_W1l[128 * LDA];
static __device__ __nv_bfloat16 d_W2h[128 * LDA], d_W2l[128 * LDA];

// ---------------------------------------------------------------- CSR build
__global__ void k_zero_deg() {
    int i = blockIdx.x * blockDim.x + threadIdx.x;
    if (i < NN / 4) reinterpret_cast<int4*>(d_deg)[i] = make_int4(0, 0, 0, 0);
}

__global__ void k_count(const int* __restrict__ dst) {
    int i = blockIdx.x * blockDim.x + threadIdx.x;
    if (i >= EE / 4) return;
    int4 d = reinterpret_cast<const int4*>(dst)[i];
    atomicAdd(&d_deg[d.x], 1);
    atomicAdd(&d_deg[d.y], 1);
    atomicAdd(&d_deg[d.z], 1);
    atomicAdd(&d_deg[d.w], 1);
}

__global__ void k_scan() {
    __shared__ int warpsum[32];
    int tid  = threadIdx.x;
    int lane = tid & 31;
    int wid  = tid >> 5;
    int running = 0;
    for (int base = 0; base < NN; base += 4096) {
        int gi = base + tid * 4;
        int4 v = make_int4(0, 0, 0, 0);
        if (gi + 3 < NN) {
            v = *reinterpret_cast<const int4*>(&d_deg[gi]);
        } else {
            if (gi     < NN) v.x = d_deg[gi];
            if (gi + 1 < NN) v.y = d_deg[gi + 1];
            if (gi + 2 < NN) v.z = d_deg[gi + 2];
            if (gi + 3 < NN) v.w = d_deg[gi + 3];
        }
        int t = v.x + v.y + v.z + v.w;
        int inc = t;
#pragma unroll
        for (int off = 1; off < 32; off <<= 1) {
            int n = __shfl_up_sync(0xffffffffu, inc, off);
            if (lane >= off) inc += n;
        }
        if (lane == 31) warpsum[wid] = inc;
        __syncthreads();
        if (wid == 0) {
            int wi = warpsum[lane];
#pragma unroll
            for (int off = 1; off < 32; off <<= 1) {
                int n = __shfl_up_sync(0xffffffffu, wi, off);
                if (lane >= off) wi += n;
            }
            warpsum[lane] = wi;
        }
        __syncthreads();
        int warpoff = (wid > 0) ? warpsum[wid - 1] : 0;
        int excl = running + warpoff + inc - t;
        if (gi < NN) {
            d_rowstart[gi] = excl; d_cursor[gi] = excl;
            d_dinv[gi] = rsqrtf((float)(v.x + 1)); excl += v.x;
        }
        if (gi + 1 < NN) {
            d_rowstart[gi + 1] = excl; d_cursor[gi + 1] = excl;
            d_dinv[gi + 1] = rsqrtf((float)(v.y + 1)); excl += v.y;
        }
        if (gi + 2 < NN) {
            d_rowstart[gi + 2] = excl; d_cursor[gi + 2] = excl;
            d_dinv[gi + 2] = rsqrtf((float)(v.z + 1)); excl += v.z;
        }
        if (gi + 3 < NN) {
            d_rowstart[gi + 3] = excl; d_cursor[gi + 3] = excl;
            d_dinv[gi + 3] = rsqrtf((float)(v.w + 1));
        }
        int tot = warpsum[31];
        __syncthreads();
        running += tot;
    }
    if (tid == 0) d_rowstart[NN] = EE;
}

__global__ void k_scatter(const int* __restrict__ src, const int* __restrict__ dst) {
    int i = blockIdx.x * blockDim.x + threadIdx.x;
    if (i >= EE / 4) return;
    int4 d = reinterpret_cast<const int4*>(dst)[i];
    int4 s = reinterpret_cast<const int4*>(src)[i];
    d_srcs[atomicAdd(&d_cursor[d.x], 1)] = s.x;
    d_srcs[atomicAdd(&d_cursor[d.y], 1)] = s.y;
    d_srcs[atomicAdd(&d_cursor[d.z], 1)] = s.z;
    d_srcs[atomicAdd(&d_cursor[d.w], 1)] = s.w;
}

// ---------------------------------------------------------------- W pre-convert
// W[k][n] fp32 -> transposed padded [n][k] bf16 hi/lo.
__global__ void k_prepw(const float* __restrict__ W,
                        __nv_bfloat16* __restrict__ oh, __nv_bfloat16* __restrict__ ol) {
    int idx = blockIdx.x * blockDim.x + threadIdx.x;   // 128*128 elements
    if (idx >= 128 * 128) return;
    int k = idx >> 7;
    int n = idx & 127;
    float v = W[(size_t)k * HH + n];
    __nv_bfloat16 h = __float2bfloat16_rn(v);
    __nv_bfloat16 l = __float2bfloat16_rn(v - __bfloat162float(h));
    oh[n * LDA + k] = h;
    ol[n * LDA + k] = l;
}

// ---------------------------------------------------------------- mma.sync GEMM
// g_hb[row] = (A[row] @ W) * (scale ? dinv[row] : 1), fp16 out.
// M=64 rows/CTA; 8 warps: wr = wid&3 (16-row slab), wc = wid>>2 (64-col half).
// smem: A hi/lo 64x136, B hi/lo copied from pre-converted global. 104448 B -> 2 CTA/SM.

#define A_TILE_B (64 * LDA * 2)      // 17408
#define B_TILE_B (128 * LDA * 2)     // 34816
#define SM_AH 0
#define SM_AL (A_TILE_B)
#define SM_BH (2 * A_TILE_B)
#define SM_BL (2 * A_TILE_B + B_TILE_B)
#define SM_TOTAL (2 * A_TILE_B + 2 * B_TILE_B)   // 104448

__device__ __forceinline__ uint32_t smem_u32(const void* p) {
    uint32_t a;
    asm("{ .reg .u64 t; cvta.to.shared.u64 t, %1; cvt.u32.u64 %0, t; }" : "=r"(a) : "l"(p));
    return a;
}
__device__ __forceinline__ void ldsm4(uint32_t* r, uint32_t addr) {
    asm volatile("ldmatrix.sync.aligned.m8n8.x4.shared.b16 {%0,%1,%2,%3}, [%4];"
                 : "=r"(r[0]), "=r"(r[1]), "=r"(r[2]), "=r"(r[3]) : "r"(addr));
}
__device__ __forceinline__ void mma_bf16(float* d, const uint32_t* a, const uint32_t* b) {
    asm volatile(
        "mma.sync.aligned.m16n8k16.row.col.f32.bf16.bf16.f32 "
        "{%0,%1,%2,%3}, {%4,%5,%6,%7}, {%8,%9}, {%0,%1,%2,%3};"
        : "+f"(d[0]), "+f"(d[1]), "+f"(d[2]), "+f"(d[3])
        : "r"(a[0]), "r"(a[1]), "r"(a[2]), "r"(a[3]), "r"(b[0]), "r"(b[1]));
}
__device__ __forceinline__ uint32_t pack_hi(float x, float y, uint32_t& lo) {
    __nv_bfloat16 h0 = __float2bfloat16_rn(x);
    __nv_bfloat16 h1 = __float2bfloat16_rn(y);
    __nv_bfloat16 l0 = __float2bfloat16_rn(x - __bfloat162float(h0));
    __nv_bfloat16 l1 = __float2bfloat16_rn(y - __bfloat162float(h1));
    lo = (uint32_t)__bfloat16_as_ushort(l0) | ((uint32_t)__bfloat16_as_ushort(l1) << 16);
    return (uint32_t)__bfloat16_as_ushort(h0) | ((uint32_t)__bfloat16_as_ushort(h1) << 16);
}

__global__ void __launch_bounds__(256, 2)
k_gemm_mma(const float* __restrict__ xin,
           const __nv_bfloat16* __restrict__ Wh, const __nv_bfloat16* __restrict__ Wl,
           int scale) {
    extern __shared__ __align__(16) char smem[];
    const float* A = xin ? xin : (const float*)h_buf;
    uint32_t sb = smem_u32(smem);
    int tid  = threadIdx.x;
    int wid  = tid >> 5;
    int lane = tid & 31;
    int row0 = blockIdx.x * 64;

    // ---- stage A rows (fp32 -> bf16 hi/lo): 64 x 64 float2 = 4096 iters ----
    for (int idx = tid; idx < 64 * 64; idx += 256) {
        int r  = idx >> 6;
        int kp = idx & 63;
        int grow = row0 + r;
        float2 v = make_float2(0.f, 0.f);
        if (grow < NN)
            v = *reinterpret_cast<const float2*>(A + (size_t)grow * HH + kp * 2);
        uint32_t lo, hi = pack_hi(v.x, v.y, lo);
        uint32_t off = (uint32_t)(r * LDA + kp * 2) * 2;
        *reinterpret_cast<uint32_t*>(smem + SM_AH + off) = hi;
        *reinterpret_cast<uint32_t*>(smem + SM_AL + off) = lo;
    }
    // ---- copy pre-converted B tiles (uint4, coalesced; 2176 16B-chunks each) ----
    {
        const uint4* gh = reinterpret_cast<const uint4*>(Wh);
        const uint4* gl = reinterpret_cast<const uint4*>(Wl);
        uint4* shv = reinterpret_cast<uint4*>(smem + SM_BH);
        uint4* slv = reinterpret_cast<uint4*>(smem + SM_BL);
        for (int i = tid; i < (128 * LDA * 2) / 16; i += 256) {
            shv[i] = gh[i];
            slv[i] = gl[i];
        }
    }
    __syncthreads();

    int wr = wid & 3;          // 16-row slab
    int wc = wid >> 2;         // 64-col half
    int m0 = wr * 16;
    float acc[8][4];
#pragma unroll
    for (int i = 0; i < 8; i++)
#pragma unroll
        for (int j = 0; j < 4; j++) acc[i][j] = 0.f;

    uint32_t a_off = (uint32_t)((m0 + (lane & 15)) * LDA + ((lane >> 4) << 3)) * 2;
    uint32_t b_off = (uint32_t)(((lane & 7) + ((lane >> 1) & 8)) * LDA + (lane & 8)) * 2;

#pragma unroll
    for (int ks = 0; ks < 8; ks++) {
        int k0 = ks * 16;
        uint32_t ah[4], al[4];
        ldsm4(ah, sb + SM_AH + a_off + k0 * 2);
        ldsm4(al, sb + SM_AL + a_off + k0 * 2);
#pragma unroll
        for (int np = 0; np < 4; np++) {
            uint32_t bh[4], bl[4];
            uint32_t bo = (uint32_t)((wc * 64 + np * 16) * LDA + k0) * 2 + b_off;
            ldsm4(bh, sb + SM_BH + bo);
            ldsm4(bl, sb + SM_BL + bo);
            mma_bf16(acc[2 * np],     ah, bh);
            mma_bf16(acc[2 * np + 1], ah, bh + 2);
            mma_bf16(acc[2 * np],     al, bh);
            mma_bf16(acc[2 * np + 1], al, bh + 2);
            mma_bf16(acc[2 * np],     ah, bl);
            mma_bf16(acc[2 * np + 1], ah, bl + 2);
        }
    }

    // ---- epilogue: optional dinv scale, store fp16 ----
    int r0 = row0 + m0 + (lane >> 2);
    int r1 = r0 + 8;
    float s0 = 1.f, s1 = 1.f;
    if (scale) {
        s0 = (r0 < NN) ? d_dinv[r0] : 0.f;
        s1 = (r1 < NN) ? d_dinv[r1] : 0.f;
    }
    int c0 = wc * 64 + (lane & 3) * 2;
#pragma unroll
    for (int nt = 0; nt < 8; nt++) {
        int col = c0 + nt * 8;
        if (r0 < NN)
            *reinterpret_cast<__half2*>(&g_hb[(size_t)r0 * HH + col]) =
                __floats2half2_rn(acc[nt][0] * s0, acc[nt][1] * s0);
        if (r1 < NN)
            *reinterpret_cast<__half2*>(&g_hb[(size_t)r1 * HH + col]) =
                __floats2half2_rn(acc[nt][2] * s1, acc[nt][3] * s1);
    }
}

// ---------------------------------------------------------------- aggregation
// pre_scaled=0 (layer 1): g unscaled -> out = dinv_i*(dinv_i*g_i + sum dinv_s*g_s) + b + x
// pre_scaled=1 (layers 2,3): g pre-scaled by dinv -> out = dinv_i*(g'_i + sum g'_s) + b + x
__global__ void k_agg(const float* __restrict__ x, const float* __restrict__ bias,
                      float* __restrict__ outp, int relu, int to_out, int pre_scaled) {
    int gtid = blockIdx.x * blockDim.x + threadIdx.x;
    int node = gtid >> 5;
    int lane = gtid & 31;
    if (node >= NN) return;

    const uint2* g2 = reinterpret_cast<const uint2*>(g_hb);
    size_t base = (size_t)node * 32;
    float dv = d_dinv[node];

    uint2 sv = g2[base + lane];
    __half2 p0 = *reinterpret_cast<__half2*>(&sv.x);
    __half2 p1 = *reinterpret_cast<__half2*>(&sv.y);
    float2 f0 = __half22float2(p0);
    float2 f1 = __half22float2(p1);
    float selfs = pre_scaled ? 1.f : dv;
    float4 acc = make_float4(f0.x * selfs, f0.y * selfs, f1.x * selfs, f1.y * selfs);

    int e0 = d_rowstart[node];
    int e1 = d_rowstart[node + 1];
    if (pre_scaled) {
        for (int e = e0; e < e1; ++e) {
            int s = d_srcs[e];
            uint2 v = g2[(size_t)s * 32 + lane];
            __half2 q0 = *reinterpret_cast<__half2*>(&v.x);
            __half2 q1 = *reinterpret_cast<__half2*>(&v.y);
            float2 g0 = __half22float2(q0);
            float2 g1 = __half22float2(q1);
            acc.x += g0.x; acc.y += g0.y; acc.z += g1.x; acc.w += g1.y;
        }
    } else {
        for (int e = e0; e < e1; ++e) {
            int s = d_srcs[e];
            float ds = d_dinv[s];
            uint2 v = g2[(size_t)s * 32 + lane];
            __half2 q0 = *reinterpret_cast<__half2*>(&v.x);
            __half2 q1 = *reinterpret_cast<__half2*>(&v.y);
            float2 g0 = __half22float2(q0);
            float2 g1 = __half22float2(q1);
            acc.x = fmaf(ds, g0.x, acc.x);
            acc.y = fmaf(ds, g0.y, acc.y);
            acc.z = fmaf(ds, g1.x, acc.z);
            acc.w = fmaf(ds, g1.y, acc.w);
        }
    }
    size_t cbase = (size_t)node * HH + lane * 4;
    float4 bb = *reinterpret_cast<const float4*>(bias + lane * 4);
    float4 xv = *reinterpret_cast<const float4*>(x + cbase);
    float4 o;
    o.x = fmaf(dv, acc.x, bb.x + xv.x);
    o.y = fmaf(dv, acc.y, bb.y + xv.y);
    o.z = fmaf(dv, acc.z, bb.z + xv.z);
    o.w = fmaf(dv, acc.w, bb.w + xv.w);
    if (relu) {
        o.x = fmaxf(o.x, 0.f); o.y = fmaxf(o.y, 0.f);
        o.z = fmaxf(o.z, 0.f); o.w = fmaxf(o.w, 0.f);
    }
    float* dstp = to_out ? outp : (float*)h_buf;
    *reinterpret_cast<float4*>(dstp + cbase) = o;
}

// ---------------------------------------------------------------- launch
extern "C" void kernel_launch(void* const* d_in, const int* in_sizes, int n_in,
                              void* d_out, int out_size) {
    const float* x   = (const float*)d_in[0];
    const int*   src = (const int*)  d_in[1];
    const int*   dst = (const int*)  d_in[2];
    const float* W1  = (const float*)d_in[3];
    const float* b1  = (const float*)d_in[4];
    const float* W2  = (const float*)d_in[5];
    const float* b2  = (const float*)d_in[6];
    float* out = (float*)d_out;

    (void)in_sizes; (void)n_in; (void)out_size;

    static int inited = 0;
    static cudaStream_t s1;
    static cudaEvent_t evFork, evJoin;
    if (!inited) {
        cudaFuncSetAttribute(k_gemm_mma, cudaFuncAttributeMaxDynamicSharedMemorySize, SM_TOTAL);
        cudaStreamCreateWithFlags(&s1, cudaStreamNonBlocking);
        cudaEventCreateWithFlags(&evFork, cudaEventDisableTiming);
        cudaEventCreateWithFlags(&evJoin, cudaEventDisableTiming);
        inited = 1;
    }

    __nv_bfloat16 *w1h, *w1l, *w2h, *w2l;
    cudaGetSymbolAddress((void**)&w1h, d_W1h);
    cudaGetSymbolAddress((void**)&w1l, d_W1l);
    cudaGetSymbolAddress((void**)&w2h, d_W2h);
    cudaGetSymbolAddress((void**)&w2l, d_W2l);

    const int gemm_grid = (NN + 63) / 64;     // 1563
    const int agg_grid  = (NN * 32 + 255) / 256;

    // Fork: CSR build + W2 prep on s1; W1 prep + GEMM1 on main stream.
    cudaEventRecord(evFork, 0);
    cudaStreamWaitEvent(s1, evFork, 0);

    k_zero_deg<<<(NN / 4 + 255) / 256, 256, 0, s1>>>();
    k_count   <<<(EE / 4 + 255) / 256, 256, 0, s1>>>(dst);
    k_scan    <<<1, 1024, 0, s1>>>();
    k_scatter <<<(EE / 4 + 255) / 256, 256, 0, s1>>>(src, dst);
    k_prepw   <<<64, 256, 0, s1>>>(W2, w2h, w2l);
    cudaEventRecord(evJoin, s1);

    k_prepw<<<64, 256>>>(W1, w1h, w1l);
    k_gemm_mma<<<gemm_grid, 256, SM_TOTAL>>>(x, w1h, w1l, /*scale=*/0);  // overlaps CSR

    cudaStreamWaitEvent(0, evJoin, 0);

    // layer 1
    k_agg<<<agg_grid, 256>>>(x, b1, out, 1, 0, /*pre_scaled=*/0);
    // layer 2
    k_gemm_mma<<<gemm_grid, 256, SM_TOTAL>>>(nullptr, w2h, w2l, /*scale=*/1);
    k_agg<<<agg_grid, 256>>>(x, b2, out, 1, 0, /*pre_scaled=*/1);
    // layer 3
    k_gemm_mma<<<gemm_grid, 256, SM_TOTAL>>>(nullptr, w2h, w2l, /*scale=*/1);
    k_agg<<<agg_grid, 256>>>(x, b2, out, 0, 1, /*pre_scaled=*/1);
}

// round 8
// speedup vs baseline: 1.4363x; 1.1239x over previous
#include <cuda_runtime.h>
#include <cuda_bf16.h>
#include <cuda_fp16.h>
#include <cstdint>

#define NN 100000
#define EE 1600000
#define HH 128

typedef unsigned long long ull;

// ---- scratch (device globals) ----
static __device__ __half g_hb[(size_t)NN * HH];   // GEMM output, fp16
static __device__ __half h_hb[(size_t)NN * HH];   // layer activations (relu'd), fp16
static __device__ float  d_dinv[NN];
static __device__ int    d_deg[NN];
static __device__ int    d_rowstart[NN + 1];
static __device__ int    d_cursor[NN];
static __device__ int    d_srcs[EE];
// pre-converted W (transposed [n][k], padded LDA=136), bf16 hi/lo
#define LDA 136
static __device__ __nv_bfloat16 d_W1h[128 * LDA], d_W1l[128 * LDA];
static __device__ __nv_bfloat16 d_W2h[128 * LDA], d_W2l[128 * LDA];

// ---------------------------------------------------------------- CSR build
__global__ void k_zero_deg() {
    int i = blockIdx.x * blockDim.x + threadIdx.x;
    if (i < NN / 4) reinterpret_cast<int4*>(d_deg)[i] = make_int4(0, 0, 0, 0);
}

__global__ void k_count(const int* __restrict__ dst) {
    int i = blockIdx.x * blockDim.x + threadIdx.x;
    if (i >= EE / 4) return;
    int4 d = reinterpret_cast<const int4*>(dst)[i];
    atomicAdd(&d_deg[d.x], 1);
    atomicAdd(&d_deg[d.y], 1);
    atomicAdd(&d_deg[d.z], 1);
    atomicAdd(&d_deg[d.w], 1);
}

__global__ void k_scan() {
    __shared__ int warpsum[32];
    int tid  = threadIdx.x;
    int lane = tid & 31;
    int wid  = tid >> 5;
    int running = 0;
    for (int base = 0; base < NN; base += 4096) {
        int gi = base + tid * 4;
        int4 v = make_int4(0, 0, 0, 0);
        if (gi + 3 < NN) {
            v = *reinterpret_cast<const int4*>(&d_deg[gi]);
        } else {
            if (gi     < NN) v.x = d_deg[gi];
            if (gi + 1 < NN) v.y = d_deg[gi + 1];
            if (gi + 2 < NN) v.z = d_deg[gi + 2];
            if (gi + 3 < NN) v.w = d_deg[gi + 3];
        }
        int t = v.x + v.y + v.z + v.w;
        int inc = t;
#pragma unroll
        for (int off = 1; off < 32; off <<= 1) {
            int n = __shfl_up_sync(0xffffffffu, inc, off);
            if (lane >= off) inc += n;
        }
        if (lane == 31) warpsum[wid] = inc;
        __syncthreads();
        if (wid == 0) {
            int wi = warpsum[lane];
#pragma unroll
            for (int off = 1; off < 32; off <<= 1) {
                int n = __shfl_up_sync(0xffffffffu, wi, off);
                if (lane >= off) wi += n;
            }
            warpsum[lane] = wi;
        }
        __syncthreads();
        int warpoff = (wid > 0) ? warpsum[wid - 1] : 0;
        int excl = running + warpoff + inc - t;
        if (gi < NN) {
            d_rowstart[gi] = excl; d_cursor[gi] = excl;
            d_dinv[gi] = rsqrtf((float)(v.x + 1)); excl += v.x;
        }
        if (gi + 1 < NN) {
            d_rowstart[gi + 1] = excl; d_cursor[gi + 1] = excl;
            d_dinv[gi + 1] = rsqrtf((float)(v.y + 1)); excl += v.y;
        }
        if (gi + 2 < NN) {
            d_rowstart[gi + 2] = excl; d_cursor[gi + 2] = excl;
            d_dinv[gi + 2] = rsqrtf((float)(v.z + 1)); excl += v.z;
        }
        if (gi + 3 < NN) {
            d_rowstart[gi + 3] = excl; d_cursor[gi + 3] = excl;
            d_dinv[gi + 3] = rsqrtf((float)(v.w + 1));
        }
        int tot = warpsum[31];
        __syncthreads();
        running += tot;
    }
    if (tid == 0) d_rowstart[NN] = EE;
}

__global__ void k_scatter(const int* __restrict__ src, const int* __restrict__ dst) {
    int i = blockIdx.x * blockDim.x + threadIdx.x;
    if (i >= EE / 4) return;
    int4 d = reinterpret_cast<const int4*>(dst)[i];
    int4 s = reinterpret_cast<const int4*>(src)[i];
    d_srcs[atomicAdd(&d_cursor[d.x], 1)] = s.x;
    d_srcs[atomicAdd(&d_cursor[d.y], 1)] = s.y;
    d_srcs[atomicAdd(&d_cursor[d.z], 1)] = s.z;
    d_srcs[atomicAdd(&d_cursor[d.w], 1)] = s.w;
}

// ---------------------------------------------------------------- W pre-convert
__global__ void k_prepw(const float* __restrict__ W,
                        __nv_bfloat16* __restrict__ oh, __nv_bfloat16* __restrict__ ol) {
    int idx = blockIdx.x * blockDim.x + threadIdx.x;
    if (idx >= 128 * 128) return;
    int k = idx >> 7;
    int n = idx & 127;
    float v = W[(size_t)k * HH + n];
    __nv_bfloat16 h = __float2bfloat16_rn(v);
    __nv_bfloat16 l = __float2bfloat16_rn(v - __bfloat162float(h));
    oh[n * LDA + k] = h;
    ol[n * LDA + k] = l;
}

// ---------------------------------------------------------------- mma.sync GEMM
#define A_TILE_B (64 * LDA * 2)
#define B_TILE_B (128 * LDA * 2)
#define SM_AH 0
#define SM_AL (A_TILE_B)
#define SM_BH (2 * A_TILE_B)
#define SM_BL (2 * A_TILE_B + B_TILE_B)
#define SM_TOTAL (2 * A_TILE_B + 2 * B_TILE_B)   // 104448

__device__ __forceinline__ uint32_t smem_u32(const void* p) {
    uint32_t a;
    asm("{ .reg .u64 t; cvta.to.shared.u64 t, %1; cvt.u32.u64 %0, t; }" : "=r"(a) : "l"(p));
    return a;
}
__device__ __forceinline__ void ldsm4(uint32_t* r, uint32_t addr) {
    asm volatile("ldmatrix.sync.aligned.m8n8.x4.shared.b16 {%0,%1,%2,%3}, [%4];"
                 : "=r"(r[0]), "=r"(r[1]), "=r"(r[2]), "=r"(r[3]) : "r"(addr));
}
__device__ __forceinline__ void mma_bf16(float* d, const uint32_t* a, const uint32_t* b) {
    asm volatile(
        "mma.sync.aligned.m16n8k16.row.col.f32.bf16.bf16.f32 "
        "{%0,%1,%2,%3}, {%4,%5,%6,%7}, {%8,%9}, {%0,%1,%2,%3};"
        : "+f"(d[0]), "+f"(d[1]), "+f"(d[2]), "+f"(d[3])
        : "r"(a[0]), "r"(a[1]), "r"(a[2]), "r"(a[3]), "r"(b[0]), "r"(b[1]));
}
__device__ __forceinline__ uint32_t pack_hi(float x, float y, uint32_t& lo) {
    __nv_bfloat16 h0 = __float2bfloat16_rn(x);
    __nv_bfloat16 h1 = __float2bfloat16_rn(y);
    __nv_bfloat16 l0 = __float2bfloat16_rn(x - __bfloat162float(h0));
    __nv_bfloat16 l1 = __float2bfloat16_rn(y - __bfloat162float(h1));
    lo = (uint32_t)__bfloat16_as_ushort(l0) | ((uint32_t)__bfloat16_as_ushort(l1) << 16);
    return (uint32_t)__bfloat16_as_ushort(h0) | ((uint32_t)__bfloat16_as_ushort(h1) << 16);
}

// A source: xf32 (layer 1) if non-null, else fp16 h_hb.
__global__ void __launch_bounds__(256, 2)
k_gemm_mma(const float* __restrict__ xf32,
           const __nv_bfloat16* __restrict__ Wh, const __nv_bfloat16* __restrict__ Wl,
           int scale) {
    extern __shared__ __align__(16) char smem[];
    uint32_t sb = smem_u32(smem);
    int tid  = threadIdx.x;
    int wid  = tid >> 5;
    int lane = tid & 31;
    int row0 = blockIdx.x * 64;

    if (xf32) {
        // fp32 staging path
        for (int idx = tid; idx < 64 * 64; idx += 256) {
            int r  = idx >> 6;
            int kp = idx & 63;
            int grow = row0 + r;
            float2 v = make_float2(0.f, 0.f);
            if (grow < NN)
                v = *reinterpret_cast<const float2*>(xf32 + (size_t)grow * HH + kp * 2);
            uint32_t lo, hi = pack_hi(v.x, v.y, lo);
            uint32_t off = (uint32_t)(r * LDA + kp * 2) * 2;
            *reinterpret_cast<uint32_t*>(smem + SM_AH + off) = hi;
            *reinterpret_cast<uint32_t*>(smem + SM_AL + off) = lo;
        }
    } else {
        // fp16 staging path: 4 cols per iter, 8B coalesced loads
        const __half* A16 = (const __half*)h_hb;
        for (int idx = tid; idx < 64 * 32; idx += 256) {
            int r  = idx >> 5;
            int k4 = (idx & 31) * 4;
            int grow = row0 + r;
            uint2 v = make_uint2(0u, 0u);
            if (grow < NN)
                v = *reinterpret_cast<const uint2*>(A16 + (size_t)grow * HH + k4);
            __half2 a01 = *reinterpret_cast<__half2*>(&v.x);
            __half2 a23 = *reinterpret_cast<__half2*>(&v.y);
            float2 f0 = __half22float2(a01);
            float2 f1 = __half22float2(a23);
            uint32_t lo0, hi0 = pack_hi(f0.x, f0.y, lo0);
            uint32_t lo1, hi1 = pack_hi(f1.x, f1.y, lo1);
            uint32_t off = (uint32_t)(r * LDA + k4) * 2;
            *reinterpret_cast<uint32_t*>(smem + SM_AH + off)     = hi0;
            *reinterpret_cast<uint32_t*>(smem + SM_AH + off + 4) = hi1;
            *reinterpret_cast<uint32_t*>(smem + SM_AL + off)     = lo0;
            *reinterpret_cast<uint32_t*>(smem + SM_AL + off + 4) = lo1;
        }
    }
    // ---- copy pre-converted B tiles ----
    {
        const uint4* gh = reinterpret_cast<const uint4*>(Wh);
        const uint4* gl = reinterpret_cast<const uint4*>(Wl);
        uint4* shv = reinterpret_cast<uint4*>(smem + SM_BH);
        uint4* slv = reinterpret_cast<uint4*>(smem + SM_BL);
        for (int i = tid; i < (128 * LDA * 2) / 16; i += 256) {
            shv[i] = gh[i];
            slv[i] = gl[i];
        }
    }
    __syncthreads();

    int wr = wid & 3;
    int wc = wid >> 2;
    int m0 = wr * 16;
    float acc[8][4];
#pragma unroll
    for (int i = 0; i < 8; i++)
#pragma unroll
        for (int j = 0; j < 4; j++) acc[i][j] = 0.f;

    uint32_t a_off = (uint32_t)((m0 + (lane & 15)) * LDA + ((lane >> 4) << 3)) * 2;
    uint32_t b_off = (uint32_t)(((lane & 7) + ((lane >> 1) & 8)) * LDA + (lane & 8)) * 2;

#pragma unroll
    for (int ks = 0; ks < 8; ks++) {
        int k0 = ks * 16;
        uint32_t ah[4], al[4];
        ldsm4(ah, sb + SM_AH + a_off + k0 * 2);
        ldsm4(al, sb + SM_AL + a_off + k0 * 2);
#pragma unroll
        for (int np = 0; np < 4; np++) {
            uint32_t bh[4], bl[4];
            uint32_t bo = (uint32_t)((wc * 64 + np * 16) * LDA + k0) * 2 + b_off;
            ldsm4(bh, sb + SM_BH + bo);
            ldsm4(bl, sb + SM_BL + bo);
            mma_bf16(acc[2 * np],     ah, bh);
            mma_bf16(acc[2 * np + 1], ah, bh + 2);
            mma_bf16(acc[2 * np],     al, bh);
            mma_bf16(acc[2 * np + 1], al, bh + 2);
            mma_bf16(acc[2 * np],     ah, bl);
            mma_bf16(acc[2 * np + 1], ah, bl + 2);
        }
    }

    int r0 = row0 + m0 + (lane >> 2);
    int r1 = r0 + 8;
    float s0 = 1.f, s1 = 1.f;
    if (scale) {
        s0 = (r0 < NN) ? d_dinv[r0] : 0.f;
        s1 = (r1 < NN) ? d_dinv[r1] : 0.f;
    }
    int c0 = wc * 64 + (lane & 3) * 2;
#pragma unroll
    for (int nt = 0; nt < 8; nt++) {
        int col = c0 + nt * 8;
        if (r0 < NN)
            *reinterpret_cast<__half2*>(&g_hb[(size_t)r0 * HH + col]) =
                __floats2half2_rn(acc[nt][0] * s0, acc[nt][1] * s0);
        if (r1 < NN)
            *reinterpret_cast<__half2*>(&g_hb[(size_t)r1 * HH + col]) =
                __floats2half2_rn(acc[nt][2] * s1, acc[nt][3] * s1);
    }
}

// ---------------------------------------------------------------- aggregation
// pre_scaled=0 (layer 1): out = dinv_i*(dinv_i*g_i + sum dinv_s*g_s) + b + x
// pre_scaled=1 (layers 2,3): g pre-scaled -> out = dinv_i*(g'_i + sum g'_s) + b + x
// to_out=0: write fp16 h_hb (with relu). to_out=1: write fp32 out.
__global__ void k_agg(const float* __restrict__ x, const float* __restrict__ bias,
                      float* __restrict__ outp, int relu, int to_out, int pre_scaled) {
    int gtid = blockIdx.x * blockDim.x + threadIdx.x;
    int node = gtid >> 5;
    int lane = gtid & 31;
    if (node >= NN) return;

    const uint2* g2 = reinterpret_cast<const uint2*>(g_hb);
    size_t base = (size_t)node * 32;
    float dv = d_dinv[node];

    uint2 sv = g2[base + lane];
    float2 f0 = __half22float2(*reinterpret_cast<__half2*>(&sv.x));
    float2 f1 = __half22float2(*reinterpret_cast<__half2*>(&sv.y));
    float selfs = pre_scaled ? 1.f : dv;
    float4 acc = make_float4(f0.x * selfs, f0.y * selfs, f1.x * selfs, f1.y * selfs);

    int e0 = d_rowstart[node];
    int e1 = d_rowstart[node + 1];
    int e = e0;
    if (pre_scaled) {
        for (; e + 4 <= e1; e += 4) {
            int s0 = d_srcs[e], s1 = d_srcs[e + 1], s2 = d_srcs[e + 2], s3 = d_srcs[e + 3];
            uint2 v0 = g2[(size_t)s0 * 32 + lane];
            uint2 v1 = g2[(size_t)s1 * 32 + lane];
            uint2 v2 = g2[(size_t)s2 * 32 + lane];
            uint2 v3 = g2[(size_t)s3 * 32 + lane];
#define ACC4(v) { \
            float2 a0 = __half22float2(*reinterpret_cast<__half2*>(&(v).x)); \
            float2 a1 = __half22float2(*reinterpret_cast<__half2*>(&(v).y)); \
            acc.x += a0.x; acc.y += a0.y; acc.z += a1.x; acc.w += a1.y; }
            ACC4(v0) ACC4(v1) ACC4(v2) ACC4(v3)
        }
        for (; e < e1; ++e) {
            uint2 v = g2[(size_t)d_srcs[e] * 32 + lane];
            ACC4(v)
        }
#undef ACC4
    } else {
        for (; e + 4 <= e1; e += 4) {
            int s0 = d_srcs[e], s1 = d_srcs[e + 1], s2 = d_srcs[e + 2], s3 = d_srcs[e + 3];
            float d0 = d_dinv[s0], d1 = d_dinv[s1], d2 = d_dinv[s2], d3 = d_dinv[s3];
            uint2 v0 = g2[(size_t)s0 * 32 + lane];
            uint2 v1 = g2[(size_t)s1 * 32 + lane];
            uint2 v2 = g2[(size_t)s2 * 32 + lane];
            uint2 v3 = g2[(size_t)s3 * 32 + lane];
#define ACCD(v, d) { \
            float2 a0 = __half22float2(*reinterpret_cast<__half2*>(&(v).x)); \
            float2 a1 = __half22float2(*reinterpret_cast<__half2*>(&(v).y)); \
            acc.x = fmaf((d), a0.x, acc.x); acc.y = fmaf((d), a0.y, acc.y); \
            acc.z = fmaf((d), a1.x, acc.z); acc.w = fmaf((d), a1.y, acc.w); }
            ACCD(v0, d0) ACCD(v1, d1) ACCD(v2, d2) ACCD(v3, d3)
        }
        for (; e < e1; ++e) {
            int s = d_srcs[e];
            float d = d_dinv[s];
            uint2 v = g2[(size_t)s * 32 + lane];
            ACCD(v, d)
        }
#undef ACCD
    }
    size_t cbase = (size_t)node * HH + lane * 4;
    float4 bb = *reinterpret_cast<const float4*>(bias + lane * 4);
    float4 xv = *reinterpret_cast<const float4*>(x + cbase);
    float4 o;
    o.x = fmaf(dv, acc.x, bb.x + xv.x);
    o.y = fmaf(dv, acc.y, bb.y + xv.y);
    o.z = fmaf(dv, acc.z, bb.z + xv.z);
    o.w = fmaf(dv, acc.w, bb.w + xv.w);
    if (relu) {
        o.x = fmaxf(o.x, 0.f); o.y = fmaxf(o.y, 0.f);
        o.z = fmaxf(o.z, 0.f); o.w = fmaxf(o.w, 0.f);
    }
    if (to_out) {
        *reinterpret_cast<float4*>(outp + cbase) = o;
    } else {
        uint2 pk;
        *reinterpret_cast<__half2*>(&pk.x) = __floats2half2_rn(o.x, o.y);
        *reinterpret_cast<__half2*>(&pk.y) = __floats2half2_rn(o.z, o.w);
        *reinterpret_cast<uint2*>(&h_hb[cbase]) = pk;
    }
}

// ---------------------------------------------------------------- launch
extern "C" void kernel_launch(void* const* d_in, const int* in_sizes, int n_in,
                              void* d_out, int out_size) {
    const float* x   = (const float*)d_in[0];
    const int*   src = (const int*)  d_in[1];
    const int*   dst = (const int*)  d_in[2];
    const float* W1  = (const float*)d_in[3];
    const float* b1  = (const float*)d_in[4];
    const float* W2  = (const float*)d_in[5];
    const float* b2  = (const float*)d_in[6];
    float* out = (float*)d_out;

    (void)in_sizes; (void)n_in; (void)out_size;

    static int inited = 0;
    static cudaStream_t s1;
    static cudaEvent_t evFork, evJoin;
    if (!inited) {
        cudaFuncSetAttribute(k_gemm_mma, cudaFuncAttributeMaxDynamicSharedMemorySize, SM_TOTAL);
        cudaStreamCreateWithFlags(&s1, cudaStreamNonBlocking);
        cudaEventCreateWithFlags(&evFork, cudaEventDisableTiming);
        cudaEventCreateWithFlags(&evJoin, cudaEventDisableTiming);
        inited = 1;
    }

    __nv_bfloat16 *w1h, *w1l, *w2h, *w2l;
    cudaGetSymbolAddress((void**)&w1h, d_W1h);
    cudaGetSymbolAddress((void**)&w1l, d_W1l);
    cudaGetSymbolAddress((void**)&w2h, d_W2h);
    cudaGetSymbolAddress((void**)&w2l, d_W2l);

    const int gemm_grid = (NN + 63) / 64;
    const int agg_grid  = (NN * 32 + 255) / 256;

    // Fork: CSR build + W2 prep on s1; W1 prep + GEMM1 on main stream.
    cudaEventRecord(evFork, 0);
    cudaStreamWaitEvent(s1, evFork, 0);

    k_zero_deg<<<(NN / 4 + 255) / 256, 256, 0, s1>>>();
    k_count   <<<(EE / 4 + 255) / 256, 256, 0, s1>>>(dst);
    k_scan    <<<1, 1024, 0, s1>>>();
    k_scatter <<<(EE / 4 + 255) / 256, 256, 0, s1>>>(src, dst);
    k_prepw   <<<64, 256, 0, s1>>>(W2, w2h, w2l);
    cudaEventRecord(evJoin, s1);

    k_prepw<<<64, 256>>>(W1, w1h, w1l);
    k_gemm_mma<<<gemm_grid, 256, SM_TOTAL>>>(x, w1h, w1l, /*scale=*/0);  // overlaps CSR

    cudaStreamWaitEvent(0, evJoin, 0);

    // layer 1
    k_agg<<<agg_grid, 256>>>(x, b1, out, 1, 0, /*pre_scaled=*/0);
    // layer 2
    k_gemm_mma<<<gemm_grid, 256, SM_TOTAL>>>(nullptr, w2h, w2l, /*scale=*/1);
    k_agg<<<agg_grid, 256>>>(x, b2, out, 1, 0, /*pre_scaled=*/1);
    // layer 3
    k_gemm_mma<<<gemm_grid, 256, SM_TOTAL>>>(nullptr, w2h, w2l, /*scale=*/1);
    k_agg<<<agg_grid, 256>>>(x, b2, out, 0, 1, /*pre_scaled=*/1);
}

// round 9
// speedup vs baseline: 1.5767x; 1.0977x over previous
#include <cuda_runtime.h>
#include <cuda_bf16.h>
#include <cuda_fp16.h>
#include <cstdint>

#define NN 100000
#define EE 1600000
#define HH 128

typedef unsigned long long ull;

// ---- scratch (device globals) ----
static __device__ __half g_hb[(size_t)NN * HH];   // GEMM output, fp16
static __device__ __half h_hb[(size_t)NN * HH];   // layer activations (relu'd), fp16
static __device__ float  d_dinv[NN];
static __device__ int    d_deg[NN];
static __device__ int    d_rowstart[NN + 1];
static __device__ int    d_cursor[NN];
static __device__ int    d_srcs[EE];
#define LDA 136
// layer-1 W: bf16 hi/lo (3-term path)
static __device__ __nv_bfloat16 d_W1h[128 * LDA], d_W1l[128 * LDA];
// layer-2/3 W: fp16 hi/lo (2-term path)
static __device__ __half d_W2h[128 * LDA], d_W2l[128 * LDA];

// ---------------------------------------------------------------- CSR build
__global__ void k_zero_deg() {
    int i = blockIdx.x * blockDim.x + threadIdx.x;
    if (i < NN / 4) reinterpret_cast<int4*>(d_deg)[i] = make_int4(0, 0, 0, 0);
}

__global__ void k_count(const int* __restrict__ dst) {
    int i = blockIdx.x * blockDim.x + threadIdx.x;
    if (i >= EE / 4) return;
    int4 d = reinterpret_cast<const int4*>(dst)[i];
    atomicAdd(&d_deg[d.x], 1);
    atomicAdd(&d_deg[d.y], 1);
    atomicAdd(&d_deg[d.z], 1);
    atomicAdd(&d_deg[d.w], 1);
}

__global__ void k_scan() {
    __shared__ int warpsum[32];
    int tid  = threadIdx.x;
    int lane = tid & 31;
    int wid  = tid >> 5;
    int running = 0;
    for (int base = 0; base < NN; base += 4096) {
        int gi = base + tid * 4;
        int4 v = make_int4(0, 0, 0, 0);
        if (gi + 3 < NN) {
            v = *reinterpret_cast<const int4*>(&d_deg[gi]);
        } else {
            if (gi     < NN) v.x = d_deg[gi];
            if (gi + 1 < NN) v.y = d_deg[gi + 1];
            if (gi + 2 < NN) v.z = d_deg[gi + 2];
            if (gi + 3 < NN) v.w = d_deg[gi + 3];
        }
        int t = v.x + v.y + v.z + v.w;
        int inc = t;
#pragma unroll
        for (int off = 1; off < 32; off <<= 1) {
            int n = __shfl_up_sync(0xffffffffu, inc, off);
            if (lane >= off) inc += n;
        }
        if (lane == 31) warpsum[wid] = inc;
        __syncthreads();
        if (wid == 0) {
            int wi = warpsum[lane];
#pragma unroll
            for (int off = 1; off < 32; off <<= 1) {
                int n = __shfl_up_sync(0xffffffffu, wi, off);
                if (lane >= off) wi += n;
            }
            warpsum[lane] = wi;
        }
        __syncthreads();
        int warpoff = (wid > 0) ? warpsum[wid - 1] : 0;
        int excl = running + warpoff + inc - t;
        if (gi < NN) {
            d_rowstart[gi] = excl; d_cursor[gi] = excl;
            d_dinv[gi] = rsqrtf((float)(v.x + 1)); excl += v.x;
        }
        if (gi + 1 < NN) {
            d_rowstart[gi + 1] = excl; d_cursor[gi + 1] = excl;
            d_dinv[gi + 1] = rsqrtf((float)(v.y + 1)); excl += v.y;
        }
        if (gi + 2 < NN) {
            d_rowstart[gi + 2] = excl; d_cursor[gi + 2] = excl;
            d_dinv[gi + 2] = rsqrtf((float)(v.z + 1)); excl += v.z;
        }
        if (gi + 3 < NN) {
            d_rowstart[gi + 3] = excl; d_cursor[gi + 3] = excl;
            d_dinv[gi + 3] = rsqrtf((float)(v.w + 1));
        }
        int tot = warpsum[31];
        __syncthreads();
        running += tot;
    }
    if (tid == 0) d_rowstart[NN] = EE;
}

__global__ void k_scatter(const int* __restrict__ src, const int* __restrict__ dst) {
    int i = blockIdx.x * blockDim.x + threadIdx.x;
    if (i >= EE / 4) return;
    int4 d = reinterpret_cast<const int4*>(dst)[i];
    int4 s = reinterpret_cast<const int4*>(src)[i];
    d_srcs[atomicAdd(&d_cursor[d.x], 1)] = s.x;
    d_srcs[atomicAdd(&d_cursor[d.y], 1)] = s.y;
    d_srcs[atomicAdd(&d_cursor[d.z], 1)] = s.z;
    d_srcs[atomicAdd(&d_cursor[d.w], 1)] = s.w;
}

// ---------------------------------------------------------------- W pre-convert
__global__ void k_prepw_bf16(const float* __restrict__ W,
                             __nv_bfloat16* __restrict__ oh, __nv_bfloat16* __restrict__ ol) {
    int idx = blockIdx.x * blockDim.x + threadIdx.x;
    if (idx >= 128 * 128) return;
    int k = idx >> 7;
    int n = idx & 127;
    float v = W[(size_t)k * HH + n];
    __nv_bfloat16 h = __float2bfloat16_rn(v);
    __nv_bfloat16 l = __float2bfloat16_rn(v - __bfloat162float(h));
    oh[n * LDA + k] = h;
    ol[n * LDA + k] = l;
}

__global__ void k_prepw_f16(const float* __restrict__ W,
                            __half* __restrict__ oh, __half* __restrict__ ol) {
    int idx = blockIdx.x * blockDim.x + threadIdx.x;
    if (idx >= 128 * 128) return;
    int k = idx >> 7;
    int n = idx & 127;
    float v = W[(size_t)k * HH + n];
    __half h = __float2half_rn(v);
    __half l = __float2half_rn(v - __half2float(h));
    oh[n * LDA + k] = h;
    ol[n * LDA + k] = l;
}

// ---------------------------------------------------------------- common mma utils
__device__ __forceinline__ uint32_t smem_u32(const void* p) {
    uint32_t a;
    asm("{ .reg .u64 t; cvta.to.shared.u64 t, %1; cvt.u32.u64 %0, t; }" : "=r"(a) : "l"(p));
    return a;
}
__device__ __forceinline__ void ldsm4(uint32_t* r, uint32_t addr) {
    asm volatile("ldmatrix.sync.aligned.m8n8.x4.shared.b16 {%0,%1,%2,%3}, [%4];"
                 : "=r"(r[0]), "=r"(r[1]), "=r"(r[2]), "=r"(r[3]) : "r"(addr));
}
__device__ __forceinline__ void mma_bf16(float* d, const uint32_t* a, const uint32_t* b) {
    asm volatile(
        "mma.sync.aligned.m16n8k16.row.col.f32.bf16.bf16.f32 "
        "{%0,%1,%2,%3}, {%4,%5,%6,%7}, {%8,%9}, {%0,%1,%2,%3};"
        : "+f"(d[0]), "+f"(d[1]), "+f"(d[2]), "+f"(d[3])
        : "r"(a[0]), "r"(a[1]), "r"(a[2]), "r"(a[3]), "r"(b[0]), "r"(b[1]));
}
__device__ __forceinline__ void mma_f16(float* d, const uint32_t* a, const uint32_t* b) {
    asm volatile(
        "mma.sync.aligned.m16n8k16.row.col.f32.f16.f16.f32 "
        "{%0,%1,%2,%3}, {%4,%5,%6,%7}, {%8,%9}, {%0,%1,%2,%3};"
        : "+f"(d[0]), "+f"(d[1]), "+f"(d[2]), "+f"(d[3])
        : "r"(a[0]), "r"(a[1]), "r"(a[2]), "r"(a[3]), "r"(b[0]), "r"(b[1]));
}
__device__ __forceinline__ uint32_t pack_hi(float x, float y, uint32_t& lo) {
    __nv_bfloat16 h0 = __float2bfloat16_rn(x);
    __nv_bfloat16 h1 = __float2bfloat16_rn(y);
    __nv_bfloat16 l0 = __float2bfloat16_rn(x - __bfloat162float(h0));
    __nv_bfloat16 l1 = __float2bfloat16_rn(y - __bfloat162float(h1));
    lo = (uint32_t)__bfloat16_as_ushort(l0) | ((uint32_t)__bfloat16_as_ushort(l1) << 16);
    return (uint32_t)__bfloat16_as_ushort(h0) | ((uint32_t)__bfloat16_as_ushort(h1) << 16);
}

#define A_TILE_B (64 * LDA * 2)      // 17408
#define B_TILE_B (128 * LDA * 2)     // 34816

// ---------------------------------------------------------------- GEMM layer 1
// 3-term bf16 split from fp32 x. Non-persistent (hidden under CSR overlap).
#define SM1_AH 0
#define SM1_AL (A_TILE_B)
#define SM1_BH (2 * A_TILE_B)
#define SM1_BL (2 * A_TILE_B + B_TILE_B)
#define SM1_TOTAL (2 * A_TILE_B + 2 * B_TILE_B)   // 104448

__global__ void __launch_bounds__(256, 2)
k_gemm1(const float* __restrict__ xf32,
        const __nv_bfloat16* __restrict__ Wh, const __nv_bfloat16* __restrict__ Wl) {
    extern __shared__ __align__(16) char smem[];
    uint32_t sb = smem_u32(smem);
    int tid  = threadIdx.x;
    int wid  = tid >> 5;
    int lane = tid & 31;
    int row0 = blockIdx.x * 64;

    for (int idx = tid; idx < 64 * 64; idx += 256) {
        int r  = idx >> 6;
        int kp = idx & 63;
        int grow = row0 + r;
        float2 v = make_float2(0.f, 0.f);
        if (grow < NN)
            v = *reinterpret_cast<const float2*>(xf32 + (size_t)grow * HH + kp * 2);
        uint32_t lo, hi = pack_hi(v.x, v.y, lo);
        uint32_t off = (uint32_t)(r * LDA + kp * 2) * 2;
        *reinterpret_cast<uint32_t*>(smem + SM1_AH + off) = hi;
        *reinterpret_cast<uint32_t*>(smem + SM1_AL + off) = lo;
    }
    {
        const uint4* gh = reinterpret_cast<const uint4*>(Wh);
        const uint4* gl = reinterpret_cast<const uint4*>(Wl);
        uint4* shv = reinterpret_cast<uint4*>(smem + SM1_BH);
        uint4* slv = reinterpret_cast<uint4*>(smem + SM1_BL);
        for (int i = tid; i < B_TILE_B / 16; i += 256) {
            shv[i] = gh[i];
            slv[i] = gl[i];
        }
    }
    __syncthreads();

    int wr = wid & 3;
    int wc = wid >> 2;
    int m0 = wr * 16;
    float acc[8][4];
#pragma unroll
    for (int i = 0; i < 8; i++)
#pragma unroll
        for (int j = 0; j < 4; j++) acc[i][j] = 0.f;

    uint32_t a_off = (uint32_t)((m0 + (lane & 15)) * LDA + ((lane >> 4) << 3)) * 2;
    uint32_t b_off = (uint32_t)(((lane & 7) + ((lane >> 1) & 8)) * LDA + (lane & 8)) * 2;

#pragma unroll
    for (int ks = 0; ks < 8; ks++) {
        int k0 = ks * 16;
        uint32_t ah[4], al[4];
        ldsm4(ah, sb + SM1_AH + a_off + k0 * 2);
        ldsm4(al, sb + SM1_AL + a_off + k0 * 2);
#pragma unroll
        for (int np = 0; np < 4; np++) {
            uint32_t bh[4], bl[4];
            uint32_t bo = (uint32_t)((wc * 64 + np * 16) * LDA + k0) * 2 + b_off;
            ldsm4(bh, sb + SM1_BH + bo);
            ldsm4(bl, sb + SM1_BL + bo);
            mma_bf16(acc[2 * np],     ah, bh);
            mma_bf16(acc[2 * np + 1], ah, bh + 2);
            mma_bf16(acc[2 * np],     al, bh);
            mma_bf16(acc[2 * np + 1], al, bh + 2);
            mma_bf16(acc[2 * np],     ah, bl);
            mma_bf16(acc[2 * np + 1], ah, bl + 2);
        }
    }

    int r0 = row0 + m0 + (lane >> 2);
    int r1 = r0 + 8;
    int c0 = wc * 64 + (lane & 3) * 2;
#pragma unroll
    for (int nt = 0; nt < 8; nt++) {
        int col = c0 + nt * 8;
        if (r0 < NN)
            *reinterpret_cast<__half2*>(&g_hb[(size_t)r0 * HH + col]) =
                __floats2half2_rn(acc[nt][0], acc[nt][1]);
        if (r1 < NN)
            *reinterpret_cast<__half2*>(&g_hb[(size_t)r1 * HH + col]) =
                __floats2half2_rn(acc[nt][2], acc[nt][3]);
    }
}

// ---------------------------------------------------------------- GEMM layers 2/3
// Persistent, 2-term f16: D = A@Wh + A@Wl (A fp16 exact). A double-buffered;
// B staged once per CTA. Epilogue scales by dinv.
#define NTILES ((NN + 63) / 64)      // 1563
#define SM2_A0 0
#define SM2_A1 (A_TILE_B)
#define SM2_BH (2 * A_TILE_B)
#define SM2_BL (2 * A_TILE_B + B_TILE_B)
#define SM2_TOTAL (2 * A_TILE_B + 2 * B_TILE_B)  // 104448

__global__ void __launch_bounds__(256, 2)
k_gemm23(const __half* __restrict__ Wh, const __half* __restrict__ Wl) {
    extern __shared__ __align__(16) char smem[];
    uint32_t sb = smem_u32(smem);
    int tid  = threadIdx.x;
    int wid  = tid >> 5;
    int lane = tid & 31;

    // stage B once
    {
        const uint4* gh = reinterpret_cast<const uint4*>(Wh);
        const uint4* gl = reinterpret_cast<const uint4*>(Wl);
        uint4* shv = reinterpret_cast<uint4*>(smem + SM2_BH);
        uint4* slv = reinterpret_cast<uint4*>(smem + SM2_BL);
        for (int i = tid; i < B_TILE_B / 16; i += 256) {
            shv[i] = gh[i];
            slv[i] = gl[i];
        }
    }

    // stage A for a tile into buffer bufsel (raw fp16 copy, 8B per iter)
    auto stageA = [&](int tile, int bufsel) {
        int row0 = tile * 64;
        char* dstb = smem + (bufsel ? SM2_A1 : SM2_A0);
        const __half* A16 = (const __half*)h_hb;
        for (int idx = tid; idx < 64 * 32; idx += 256) {
            int r  = idx >> 5;
            int k4 = (idx & 31) * 4;
            int grow = row0 + r;
            uint2 v = make_uint2(0u, 0u);
            if (grow < NN)
                v = *reinterpret_cast<const uint2*>(A16 + (size_t)grow * HH + k4);
            *reinterpret_cast<uint2*>(dstb + (uint32_t)(r * LDA + k4) * 2) = v;
        }
    };

    int wr = wid & 3;
    int wc = wid >> 2;
    int m0 = wr * 16;
    uint32_t a_off = (uint32_t)((m0 + (lane & 15)) * LDA + ((lane >> 4) << 3)) * 2;
    uint32_t b_off = (uint32_t)(((lane & 7) + ((lane >> 1) & 8)) * LDA + (lane & 8)) * 2;

    int t0 = blockIdx.x;
    if (t0 < NTILES) stageA(t0, 0);
    __syncthreads();

    int buf = 0;
    for (int t = t0; t < NTILES; t += gridDim.x, buf ^= 1) {
        int nxt = t + gridDim.x;
        if (nxt < NTILES) stageA(nxt, buf ^ 1);   // overlaps with mma below

        uint32_t abase = sb + (buf ? SM2_A1 : SM2_A0) + a_off;
        float acc[8][4];
#pragma unroll
        for (int i = 0; i < 8; i++)
#pragma unroll
            for (int j = 0; j < 4; j++) acc[i][j] = 0.f;

#pragma unroll
        for (int ks = 0; ks < 8; ks++) {
            int k0 = ks * 16;
            uint32_t a[4];
            ldsm4(a, abase + k0 * 2);
#pragma unroll
            for (int np = 0; np < 4; np++) {
                uint32_t bh[4], bl[4];
                uint32_t bo = (uint32_t)((wc * 64 + np * 16) * LDA + k0) * 2 + b_off;
                ldsm4(bh, sb + SM2_BH + bo);
                ldsm4(bl, sb + SM2_BL + bo);
                mma_f16(acc[2 * np],     a, bh);
                mma_f16(acc[2 * np + 1], a, bh + 2);
                mma_f16(acc[2 * np],     a, bl);
                mma_f16(acc[2 * np + 1], a, bl + 2);
            }
        }

        int row0 = t * 64;
        int r0 = row0 + m0 + (lane >> 2);
        int r1 = r0 + 8;
        float s0 = (r0 < NN) ? d_dinv[r0] : 0.f;
        float s1 = (r1 < NN) ? d_dinv[r1] : 0.f;
        int c0 = wc * 64 + (lane & 3) * 2;
#pragma unroll
        for (int nt = 0; nt < 8; nt++) {
            int col = c0 + nt * 8;
            if (r0 < NN)
                *reinterpret_cast<__half2*>(&g_hb[(size_t)r0 * HH + col]) =
                    __floats2half2_rn(acc[nt][0] * s0, acc[nt][1] * s0);
            if (r1 < NN)
                *reinterpret_cast<__half2*>(&g_hb[(size_t)r1 * HH + col]) =
                    __floats2half2_rn(acc[nt][2] * s1, acc[nt][3] * s1);
        }
        __syncthreads();
    }
}

// ---------------------------------------------------------------- aggregation
__global__ void k_agg(const float* __restrict__ x, const float* __restrict__ bias,
                      float* __restrict__ outp, int relu, int to_out, int pre_scaled) {
    int gtid = blockIdx.x * blockDim.x + threadIdx.x;
    int node = gtid >> 5;
    int lane = gtid & 31;
    if (node >= NN) return;

    const uint2* g2 = reinterpret_cast<const uint2*>(g_hb);
    size_t base = (size_t)node * 32;
    float dv = d_dinv[node];

    uint2 sv = g2[base + lane];
    float2 f0 = __half22float2(*reinterpret_cast<__half2*>(&sv.x));
    float2 f1 = __half22float2(*reinterpret_cast<__half2*>(&sv.y));
    float selfs = pre_scaled ? 1.f : dv;
    float4 acc = make_float4(f0.x * selfs, f0.y * selfs, f1.x * selfs, f1.y * selfs);

    int e0 = d_rowstart[node];
    int e1 = d_rowstart[node + 1];
    int e = e0;
    if (pre_scaled) {
        for (; e + 4 <= e1; e += 4) {
            int s0 = d_srcs[e], s1 = d_srcs[e + 1], s2 = d_srcs[e + 2], s3 = d_srcs[e + 3];
            uint2 v0 = g2[(size_t)s0 * 32 + lane];
            uint2 v1 = g2[(size_t)s1 * 32 + lane];
            uint2 v2 = g2[(size_t)s2 * 32 + lane];
            uint2 v3 = g2[(size_t)s3 * 32 + lane];
#define ACC4(v) { \
            float2 a0 = __half22float2(*reinterpret_cast<__half2*>(&(v).x)); \
            float2 a1 = __half22float2(*reinterpret_cast<__half2*>(&(v).y)); \
            acc.x += a0.x; acc.y += a0.y; acc.z += a1.x; acc.w += a1.y; }
            ACC4(v0) ACC4(v1) ACC4(v2) ACC4(v3)
        }
        for (; e < e1; ++e) {
            uint2 v = g2[(size_t)d_srcs[e] * 32 + lane];
            ACC4(v)
        }
#undef ACC4
    } else {
        for (; e + 4 <= e1; e += 4) {
            int s0 = d_srcs[e], s1 = d_srcs[e + 1], s2 = d_srcs[e + 2], s3 = d_srcs[e + 3];
            float d0 = d_dinv[s0], d1 = d_dinv[s1], d2 = d_dinv[s2], d3 = d_dinv[s3];
            uint2 v0 = g2[(size_t)s0 * 32 + lane];
            uint2 v1 = g2[(size_t)s1 * 32 + lane];
            uint2 v2 = g2[(size_t)s2 * 32 + lane];
            uint2 v3 = g2[(size_t)s3 * 32 + lane];
#define ACCD(v, d) { \
            float2 a0 = __half22float2(*reinterpret_cast<__half2*>(&(v).x)); \
            float2 a1 = __half22float2(*reinterpret_cast<__half2*>(&(v).y)); \
            acc.x = fmaf((d), a0.x, acc.x); acc.y = fmaf((d), a0.y, acc.y); \
            acc.z = fmaf((d), a1.x, acc.z); acc.w = fmaf((d), a1.y, acc.w); }
            ACCD(v0, d0) ACCD(v1, d1) ACCD(v2, d2) ACCD(v3, d3)
        }
        for (; e < e1; ++e) {
            int s = d_srcs[e];
            float d = d_dinv[s];
            uint2 v = g2[(size_t)s * 32 + lane];
            ACCD(v, d)
        }
#undef ACCD
    }
    size_t cbase = (size_t)node * HH + lane * 4;
    float4 bb = *reinterpret_cast<const float4*>(bias + lane * 4);
    float4 xv = *reinterpret_cast<const float4*>(x + cbase);
    float4 o;
    o.x = fmaf(dv, acc.x, bb.x + xv.x);
    o.y = fmaf(dv, acc.y, bb.y + xv.y);
    o.z = fmaf(dv, acc.z, bb.z + xv.z);
    o.w = fmaf(dv, acc.w, bb.w + xv.w);
    if (relu) {
        o.x = fmaxf(o.x, 0.f); o.y = fmaxf(o.y, 0.f);
        o.z = fmaxf(o.z, 0.f); o.w = fmaxf(o.w, 0.f);
    }
    if (to_out) {
        *reinterpret_cast<float4*>(outp + cbase) = o;
    } else {
        uint2 pk;
        *reinterpret_cast<__half2*>(&pk.x) = __floats2half2_rn(o.x, o.y);
        *reinterpret_cast<__half2*>(&pk.y) = __floats2half2_rn(o.z, o.w);
        *reinterpret_cast<uint2*>(&h_hb[cbase]) = pk;
    }
}

// ---------------------------------------------------------------- launch
extern "C" void kernel_launch(void* const* d_in, const int* in_sizes, int n_in,
                              void* d_out, int out_size) {
    const float* x   = (const float*)d_in[0];
    const int*   src = (const int*)  d_in[1];
    const int*   dst = (const int*)  d_in[2];
    const float* W1  = (const float*)d_in[3];
    const float* b1  = (const float*)d_in[4];
    const float* W2  = (const float*)d_in[5];
    const float* b2  = (const float*)d_in[6];
    float* out = (float*)d_out;

    (void)in_sizes; (void)n_in; (void)out_size;

    static int inited = 0;
    static cudaStream_t s1;
    static cudaEvent_t evFork, evJoin;
    if (!inited) {
        cudaFuncSetAttribute(k_gemm1,  cudaFuncAttributeMaxDynamicSharedMemorySize, SM1_TOTAL);
        cudaFuncSetAttribute(k_gemm23, cudaFuncAttributeMaxDynamicSharedMemorySize, SM2_TOTAL);
        cudaStreamCreateWithFlags(&s1, cudaStreamNonBlocking);
        cudaEventCreateWithFlags(&evFork, cudaEventDisableTiming);
        cudaEventCreateWithFlags(&evJoin, cudaEventDisableTiming);
        inited = 1;
    }

    __nv_bfloat16 *w1h, *w1l;
    __half *w2h, *w2l;
    cudaGetSymbolAddress((void**)&w1h, d_W1h);
    cudaGetSymbolAddress((void**)&w1l, d_W1l);
    cudaGetSymbolAddress((void**)&w2h, d_W2h);
    cudaGetSymbolAddress((void**)&w2l, d_W2l);

    const int gemm1_grid = NTILES;            // 1563
    const int gemm23_grid = 296;              // persistent: 2 CTAs x 148 SMs
    const int agg_grid  = (NN * 32 + 255) / 256;

    // Fork: CSR build + W2 prep on s1; W1 prep + GEMM1 on main stream.
    cudaEventRecord(evFork, 0);
    cudaStreamWaitEvent(s1, evFork, 0);

    k_zero_deg<<<(NN / 4 + 255) / 256, 256, 0, s1>>>();
    k_count   <<<(EE / 4 + 255) / 256, 256, 0, s1>>>(dst);
    k_scan    <<<1, 1024, 0, s1>>>();
    k_scatter <<<(EE / 4 + 255) / 256, 256, 0, s1>>>(src, dst);
    k_prepw_f16<<<64, 256, 0, s1>>>(W2, w2h, w2l);
    cudaEventRecord(evJoin, s1);

    k_prepw_bf16<<<64, 256>>>(W1, w1h, w1l);
    k_gemm1<<<gemm1_grid, 256, SM1_TOTAL>>>(x, w1h, w1l);   // overlaps CSR

    cudaStreamWaitEvent(0, evJoin, 0);

    // layer 1 (g unscaled -> agg applies dinv[src])
    k_agg<<<agg_grid, 256>>>(x, b1, out, 1, 0, /*pre_scaled=*/0);
    // layer 2
    k_gemm23<<<gemm23_grid, 256, SM2_TOTAL>>>(w2h, w2l);
    k_agg<<<agg_grid, 256>>>(x, b2, out, 1, 0, /*pre_scaled=*/1);
    // layer 3
    k_gemm23<<<gemm23_grid, 256, SM2_TOTAL>>>(w2h, w2l);
    k_agg<<<agg_grid, 256>>>(x, b2, out, 0, 1, /*pre_scaled=*/1);
}